// round 1
// baseline (speedup 1.0000x reference)
#include <cuda_runtime.h>
#include <math.h>

// Problem constants
#define BB   2
#define SS   2048
#define DD   1024
#define HH   16
#define HDIM 64
#define MM   (BB*SS)          // 4096 rows
#define RMS_EPS 1e-8f

// Scratch (module-load allocated; allowed by harness rules)
__device__ float g_q[BB*HH*SS*HDIM];    // [B,H,S,HD]
__device__ float g_k[BB*HH*SS*HDIM];
__device__ float g_v[BB*HH*SS*HDIM];
__device__ float g_ctx[MM*DD];          // [B,S,D]
__device__ float g_x[MM*DD];            // post-proj + residual

// ---------------------------------------------------------------------------
// Kernel 1: Y = X @ W^T  (M=4096, N=1024, K=1024), W selected by blockIdx.z,
// epilogue: rotary (pairs along head dim) + scatter into [B,H,S,HD].
// ---------------------------------------------------------------------------
__global__ __launch_bounds__(256) void qkv_rope_kernel(
    const float* __restrict__ X,
    const float* __restrict__ wq, const float* __restrict__ wk,
    const float* __restrict__ wv,
    const float* __restrict__ sinb, const float* __restrict__ cosb)
{
    __shared__ float As[16][68];   // [k][m]
    __shared__ float Bs[16][68];   // [k][n]
    const int tid = threadIdx.x;
    const int tx = tid & 15, ty = tid >> 4;
    const int m0 = blockIdx.y << 6;
    const int n0 = blockIdx.x << 6;
    const float* W  = (blockIdx.z == 0) ? wq : (blockIdx.z == 1 ? wk : wv);
    float* outp     = (blockIdx.z == 0) ? g_q : (blockIdx.z == 1 ? g_k : g_v);

    float acc[4][4];
#pragma unroll
    for (int i = 0; i < 4; i++)
#pragma unroll
        for (int j = 0; j < 4; j++) acc[i][j] = 0.f;

    for (int k0 = 0; k0 < DD; k0 += 16) {
#pragma unroll
        for (int r = 0; r < 4; r++) {
            int idx = tid + (r << 8);
            int row = idx >> 4, col = idx & 15;
            As[col][row] = X[(m0 + row) * DD + k0 + col];
            Bs[col][row] = W[(n0 + row) * DD + k0 + col];
        }
        __syncthreads();
#pragma unroll
        for (int kk = 0; kk < 16; kk++) {
            float4 a = *reinterpret_cast<const float4*>(&As[kk][ty << 2]);
            float4 b = *reinterpret_cast<const float4*>(&Bs[kk][tx << 2]);
            acc[0][0] += a.x*b.x; acc[0][1] += a.x*b.y; acc[0][2] += a.x*b.z; acc[0][3] += a.x*b.w;
            acc[1][0] += a.y*b.x; acc[1][1] += a.y*b.y; acc[1][2] += a.y*b.z; acc[1][3] += a.y*b.w;
            acc[2][0] += a.z*b.x; acc[2][1] += a.z*b.y; acc[2][2] += a.z*b.z; acc[2][3] += a.z*b.w;
            acc[3][0] += a.w*b.x; acc[3][1] += a.w*b.y; acc[3][2] += a.w*b.z; acc[3][3] += a.w*b.w;
        }
        __syncthreads();
    }

    const int h = n0 >> 6;  // one head per 64-col block
#pragma unroll
    for (int i = 0; i < 4; i++) {
        int m  = m0 + (ty << 2) + i;
        int bb = m >> 11;          // / SS
        int s  = m & (SS - 1);
#pragma unroll
        for (int j = 0; j < 4; j += 2) {
            int n  = n0 + (tx << 2) + j;
            int hd = n & 63;
            int ir = hd >> 1;
            float sn = sinb[s * 32 + ir];
            float cs = cosb[s * 32 + ir];
            float x1 = acc[i][j], x2 = acc[i][j + 1];
            int base = ((bb * HH + h) * SS + s) * HDIM + hd;
            outp[base]     = x1 * cs - x2 * sn;
            outp[base + 1] = x2 * cs + x1 * sn;
        }
    }
}

// ---------------------------------------------------------------------------
// Kernel 2: flash-style attention. One block = (b,h) x 64-query tile.
// 16x16 threads, each owns a 4x4 patch of the 64x64 score tile and a
// 4(rows)x4(dims) patch of O. Online softmax; P staged through smem for PV.
// ---------------------------------------------------------------------------
#define PSTR 65
#define ATTN_SMEM (4 * 64 * PSTR * (int)sizeof(float))   // 66560 B

__global__ __launch_bounds__(256) void attn_kernel()
{
    extern __shared__ float sm[];
    float* Qs = sm;                  // [d][r]
    float* Ks = sm + 64 * PSTR;      // [d][c]
    float* Vs = sm + 2 * 64 * PSTR;  // [c][dd]
    float* Ps = sm + 3 * 64 * PSTR;  // [c][r]

    const int tid = threadIdx.x;
    const int tx = tid & 15, ty = tid >> 4;
    const int q0 = blockIdx.x << 6;
    const int bh = blockIdx.y;
    const float* qp = g_q + (size_t)bh * SS * HDIM;
    const float* kp = g_k + (size_t)bh * SS * HDIM;
    const float* vp = g_v + (size_t)bh * SS * HDIM;

    // Q tile, transposed [d][r]
#pragma unroll
    for (int rep = 0; rep < 16; rep++) {
        int idx = tid + (rep << 8);
        int r = idx >> 6, d = idx & 63;
        Qs[d * PSTR + r] = qp[(q0 + r) * HDIM + d];
    }

    float o[4][4];
    float m_prev[4], l[4];
#pragma unroll
    for (int i = 0; i < 4; i++) {
        m_prev[i] = -1e30f; l[i] = 0.f;
#pragma unroll
        for (int j = 0; j < 4; j++) o[i][j] = 0.f;
    }

    for (int kt = 0; kt < SS; kt += 64) {
        __syncthreads();   // protect Ks/Vs/Ps from previous iteration readers
#pragma unroll
        for (int rep = 0; rep < 16; rep++) {
            int idx = tid + (rep << 8);
            int c = idx >> 6, d = idx & 63;
            Ks[d * PSTR + c] = kp[(kt + c) * HDIM + d];
            Vs[c * PSTR + d] = vp[(kt + c) * HDIM + d];
        }
        __syncthreads();

        // S = Q K^T
        float sacc[4][4];
#pragma unroll
        for (int i = 0; i < 4; i++)
#pragma unroll
            for (int j = 0; j < 4; j++) sacc[i][j] = 0.f;

#pragma unroll 8
        for (int d = 0; d < 64; d++) {
            const float* qrow = &Qs[d * PSTR + (ty << 2)];
            const float* krow = &Ks[d * PSTR + (tx << 2)];
            float a0 = qrow[0], a1 = qrow[1], a2 = qrow[2], a3 = qrow[3];
            float b0 = krow[0], b1 = krow[1], b2 = krow[2], b3 = krow[3];
            sacc[0][0] += a0*b0; sacc[0][1] += a0*b1; sacc[0][2] += a0*b2; sacc[0][3] += a0*b3;
            sacc[1][0] += a1*b0; sacc[1][1] += a1*b1; sacc[1][2] += a1*b2; sacc[1][3] += a1*b3;
            sacc[2][0] += a2*b0; sacc[2][1] += a2*b1; sacc[2][2] += a2*b2; sacc[2][3] += a2*b3;
            sacc[3][0] += a3*b0; sacc[3][1] += a3*b1; sacc[3][2] += a3*b2; sacc[3][3] += a3*b3;
        }

        // online softmax per row; rows live in 16-lane groups (offsets <=8 stay in group)
#pragma unroll
        for (int i = 0; i < 4; i++) {
            const float SCL = 0.125f;  // 1/sqrt(64)
            float s0 = sacc[i][0]*SCL, s1 = sacc[i][1]*SCL;
            float s2 = sacc[i][2]*SCL, s3 = sacc[i][3]*SCL;
            float rmax = fmaxf(fmaxf(s0, s1), fmaxf(s2, s3));
#pragma unroll
            for (int off = 8; off > 0; off >>= 1)
                rmax = fmaxf(rmax, __shfl_xor_sync(0xffffffffu, rmax, off));
            float mn   = fmaxf(m_prev[i], rmax);
            float corr = __expf(m_prev[i] - mn);
            float p0 = __expf(s0 - mn), p1 = __expf(s1 - mn);
            float p2 = __expf(s2 - mn), p3 = __expf(s3 - mn);
            float rs = (p0 + p1) + (p2 + p3);
#pragma unroll
            for (int off = 8; off > 0; off >>= 1)
                rs += __shfl_xor_sync(0xffffffffu, rs, off);
            l[i] = l[i] * corr + rs;
            m_prev[i] = mn;
            o[i][0] *= corr; o[i][1] *= corr; o[i][2] *= corr; o[i][3] *= corr;
            int r = (ty << 2) + i;
            Ps[((tx << 2) + 0) * PSTR + r] = p0;
            Ps[((tx << 2) + 1) * PSTR + r] = p1;
            Ps[((tx << 2) + 2) * PSTR + r] = p2;
            Ps[((tx << 2) + 3) * PSTR + r] = p3;
        }
        __syncthreads();

        // O += P @ V
#pragma unroll 8
        for (int c = 0; c < 64; c++) {
            const float* prow = &Ps[c * PSTR + (ty << 2)];
            const float* vrow = &Vs[c * PSTR + (tx << 2)];
            float a0 = prow[0], a1 = prow[1], a2 = prow[2], a3 = prow[3];
            float b0 = vrow[0], b1 = vrow[1], b2 = vrow[2], b3 = vrow[3];
            o[0][0] += a0*b0; o[0][1] += a0*b1; o[0][2] += a0*b2; o[0][3] += a0*b3;
            o[1][0] += a1*b0; o[1][1] += a1*b1; o[1][2] += a1*b2; o[1][3] += a1*b3;
            o[2][0] += a2*b0; o[2][1] += a2*b1; o[2][2] += a2*b2; o[2][3] += a2*b3;
            o[3][0] += a3*b0; o[3][1] += a3*b1; o[3][2] += a3*b2; o[3][3] += a3*b3;
        }
    }

    // write ctx in [B,S,D] layout
    const int bb = bh >> 4;
    const int h  = bh & 15;
#pragma unroll
    for (int i = 0; i < 4; i++) {
        float inv = 1.0f / l[i];
        int s = q0 + (ty << 2) + i;
        int rowbase = (bb * SS + s) * DD + h * HDIM + (tx << 2);
        g_ctx[rowbase + 0] = o[i][0] * inv;
        g_ctx[rowbase + 1] = o[i][1] * inv;
        g_ctx[rowbase + 2] = o[i][2] * inv;
        g_ctx[rowbase + 3] = o[i][3] * inv;
    }
}

// ---------------------------------------------------------------------------
// Kernel 3: X = ctx @ wo^T + bo + hidden   (residual fused)
// ---------------------------------------------------------------------------
__global__ __launch_bounds__(256) void oproj_kernel(
    const float* __restrict__ hidden,
    const float* __restrict__ wo, const float* __restrict__ bo)
{
    __shared__ float As[16][68];
    __shared__ float Bs[16][68];
    const int tid = threadIdx.x;
    const int tx = tid & 15, ty = tid >> 4;
    const int m0 = blockIdx.y << 6;
    const int n0 = blockIdx.x << 6;

    float acc[4][4];
#pragma unroll
    for (int i = 0; i < 4; i++)
#pragma unroll
        for (int j = 0; j < 4; j++) acc[i][j] = 0.f;

    for (int k0 = 0; k0 < DD; k0 += 16) {
#pragma unroll
        for (int r = 0; r < 4; r++) {
            int idx = tid + (r << 8);
            int row = idx >> 4, col = idx & 15;
            As[col][row] = g_ctx[(m0 + row) * DD + k0 + col];
            Bs[col][row] = wo[(n0 + row) * DD + k0 + col];
        }
        __syncthreads();
#pragma unroll
        for (int kk = 0; kk < 16; kk++) {
            float4 a = *reinterpret_cast<const float4*>(&As[kk][ty << 2]);
            float4 b = *reinterpret_cast<const float4*>(&Bs[kk][tx << 2]);
            acc[0][0] += a.x*b.x; acc[0][1] += a.x*b.y; acc[0][2] += a.x*b.z; acc[0][3] += a.x*b.w;
            acc[1][0] += a.y*b.x; acc[1][1] += a.y*b.y; acc[1][2] += a.y*b.z; acc[1][3] += a.y*b.w;
            acc[2][0] += a.z*b.x; acc[2][1] += a.z*b.y; acc[2][2] += a.z*b.z; acc[2][3] += a.z*b.w;
            acc[3][0] += a.w*b.x; acc[3][1] += a.w*b.y; acc[3][2] += a.w*b.z; acc[3][3] += a.w*b.w;
        }
        __syncthreads();
    }

#pragma unroll
    for (int i = 0; i < 4; i++) {
        int m = m0 + (ty << 2) + i;
#pragma unroll
        for (int j = 0; j < 4; j++) {
            int n = n0 + (tx << 2) + j;
            g_x[m * DD + n] = acc[i][j] + bo[n] + hidden[m * DD + n];
        }
    }
}

// ---------------------------------------------------------------------------
// Kernel 4: RMS norm per row of g_x (rms = sqrt(mean(x^2)); eps added to rms)
// ---------------------------------------------------------------------------
__global__ __launch_bounds__(256) void rmsnorm_kernel(
    const float* __restrict__ scale, float* __restrict__ out)
{
    __shared__ float red[8];
    __shared__ float s_tot;
    const int row = blockIdx.x;
    const int tid = threadIdx.x;
    const float4* xr = reinterpret_cast<const float4*>(g_x + (size_t)row * DD);
    float4 xv = xr[tid];
    float ss = xv.x*xv.x + xv.y*xv.y + xv.z*xv.z + xv.w*xv.w;
#pragma unroll
    for (int off = 16; off > 0; off >>= 1)
        ss += __shfl_xor_sync(0xffffffffu, ss, off);
    if ((tid & 31) == 0) red[tid >> 5] = ss;
    __syncthreads();
    if (tid == 0) {
        float t = 0.f;
#pragma unroll
        for (int w = 0; w < 8; w++) t += red[w];
        s_tot = t;
    }
    __syncthreads();
    float rms = sqrtf(s_tot * (1.0f / DD));
    float inv = 1.0f / (rms + RMS_EPS);
    float4 sc = reinterpret_cast<const float4*>(scale)[tid];
    float4 ov;
    ov.x = xv.x * sc.x * inv;
    ov.y = xv.y * sc.y * inv;
    ov.z = xv.z * sc.z * inv;
    ov.w = xv.w * sc.w * inv;
    reinterpret_cast<float4*>(out)[(size_t)row * (DD / 4) + tid] = ov;
}

// ---------------------------------------------------------------------------
extern "C" void kernel_launch(void* const* d_in, const int* in_sizes, int n_in,
                              void* d_out, int out_size)
{
    const float* hidden = (const float*)d_in[0];
    const float* sinb   = (const float*)d_in[1];
    const float* cosb   = (const float*)d_in[2];
    const float* wq     = (const float*)d_in[3];
    const float* wk     = (const float*)d_in[4];
    const float* wv     = (const float*)d_in[5];
    const float* wo     = (const float*)d_in[6];
    const float* bo     = (const float*)d_in[7];
    const float* scale  = (const float*)d_in[8];
    float* out = (float*)d_out;

    cudaFuncSetAttribute(attn_kernel,
                         cudaFuncAttributeMaxDynamicSharedMemorySize, ATTN_SMEM);

    qkv_rope_kernel<<<dim3(DD / 64, MM / 64, 3), 256>>>(hidden, wq, wk, wv, sinb, cosb);
    attn_kernel<<<dim3(SS / 64, BB * HH), 256, ATTN_SMEM>>>();
    oproj_kernel<<<dim3(DD / 64, MM / 64), 256>>>(hidden, wo, bo);
    rmsnorm_kernel<<<MM, 256>>>(scale, out);
}

// round 3
// speedup vs baseline: 2.7319x; 2.7319x over previous
#include <cuda_runtime.h>
#include <math.h>
#include <stdint.h>

// Problem constants
#define BB   2
#define SS   2048
#define DD   1024
#define HH   16
#define HDIM 64
#define MM   (BB*SS)          // 4096 rows
#define RMS_EPS 1e-8f

// Scratch
__device__ float g_q[BB*HH*SS*HDIM];    // [B,H,S,HD]
__device__ float g_k[BB*HH*SS*HDIM];
__device__ float g_v[BB*HH*SS*HDIM];
__device__ float g_ctx[MM*DD];          // [B,S,D]
__device__ float g_x[MM*DD];            // post-proj + residual

// ---------------------------------------------------------------------------
// helpers
// ---------------------------------------------------------------------------
__device__ __forceinline__ uint32_t smem_u32(const void* p) {
    uint32_t a;
    asm("{ .reg .u64 t; cvta.to.shared.u64 t, %1; cvt.u32.u64 %0, t; }"
        : "=r"(a) : "l"(p));
    return a;
}

__device__ __forceinline__ uint32_t f2tf32(float x) {
    uint32_t r;
    asm("cvt.rna.tf32.f32 %0, %1;" : "=r"(r) : "f"(x));
    return r;
}

// D += A(16x8) * B(8x8), tf32
__device__ __forceinline__ void mma_tf32(float* d, const uint32_t* a, const uint32_t* b) {
    asm volatile(
        "mma.sync.aligned.m16n8k8.row.col.f32.tf32.tf32.f32 "
        "{%0,%1,%2,%3}, {%4,%5,%6,%7}, {%8,%9}, {%0,%1,%2,%3};"
        : "+f"(d[0]), "+f"(d[1]), "+f"(d[2]), "+f"(d[3])
        : "r"(a[0]), "r"(a[1]), "r"(a[2]), "r"(a[3]), "r"(b[0]), "r"(b[1]));
}

#define CP_ASYNC16(saddr, gptr) \
    asm volatile("cp.async.cg.shared.global [%0], [%1], 16;" :: "r"(saddr), "l"(gptr))
#define CP_COMMIT() asm volatile("cp.async.commit_group;")
#define CP_WAIT(N)  asm volatile("cp.async.wait_group %0;" :: "n"(N))

// ---------------------------------------------------------------------------
// Projection GEMM: Y[128,128] tile of A[M,1024] @ W[1024,1024]^T
// 256 threads = 8 warps (2 x 4), warp tile 64x32, KC=16, cp.async double buffer
// ---------------------------------------------------------------------------
#define KC   16
#define SA   20                      // smem row stride (floats)
#define GEMM_SMEM_FLOATS (128 * SA)  // per tile buffer

struct Frag { float acc[4][4][4]; }; // [mi][ni][4]

// Mainloop computes acc for tile (m0,n0); A row-major [*,1024], W row-major [N,1024]
__device__ __forceinline__ void gemm_mainloop_mma(
    float (&acc)[4][4][4],
    const float* __restrict__ A, const float* __restrict__ W,
    int m0, int n0, float* As, float* Bs /* each 2*GEMM_SMEM_FLOATS */)
{
    const int tid  = threadIdx.x;
    const int wid  = tid >> 5, lane = tid & 31;
    const int wm = wid & 1, wn = wid >> 1;
    const int gid = lane >> 2, tig = lane & 3;

    const uint32_t as_base = smem_u32(As);
    const uint32_t bs_base = smem_u32(Bs);

#pragma unroll
    for (int mi = 0; mi < 4; mi++)
#pragma unroll
        for (int ni = 0; ni < 4; ni++)
#pragma unroll
            for (int c = 0; c < 4; c++) acc[mi][ni][c] = 0.f;

    // issue tile k0 into buffer buf
    auto issue = [&](int buf, int k0) {
#pragma unroll
        for (int r = 0; r < 2; r++) {
            int idx = tid + (r << 8);      // 0..511
            int row = idx >> 2, c4 = idx & 3;
            uint32_t soff = (uint32_t)((buf * GEMM_SMEM_FLOATS + row * SA + c4 * 4) * 4);
            CP_ASYNC16(as_base + soff, A + (size_t)(m0 + row) * DD + k0 + c4 * 4);
            CP_ASYNC16(bs_base + soff, W + (size_t)(n0 + row) * DD + k0 + c4 * 4);
        }
        CP_COMMIT();
    };

    issue(0, 0);
    for (int k0 = 0; k0 < DD; k0 += KC) {
        int buf = (k0 >> 4) & 1;
        bool has_next = (k0 + KC) < DD;
        if (has_next) {
            issue(buf ^ 1, k0 + KC);
            CP_WAIT(1);
        } else {
            CP_WAIT(0);
        }
        __syncthreads();

        const float* At = As + buf * GEMM_SMEM_FLOATS;
        const float* Bt = Bs + buf * GEMM_SMEM_FLOATS;
#pragma unroll
        for (int kk = 0; kk < KC; kk += 8) {
            uint32_t af[4][4], bf[4][2];
#pragma unroll
            for (int mi = 0; mi < 4; mi++) {
                int r = wm * 64 + mi * 16 + gid;
                af[mi][0] = f2tf32(At[r * SA + kk + tig]);
                af[mi][1] = f2tf32(At[(r + 8) * SA + kk + tig]);
                af[mi][2] = f2tf32(At[r * SA + kk + tig + 4]);
                af[mi][3] = f2tf32(At[(r + 8) * SA + kk + tig + 4]);
            }
#pragma unroll
            for (int ni = 0; ni < 4; ni++) {
                int c = wn * 32 + ni * 8 + gid;
                bf[ni][0] = f2tf32(Bt[c * SA + kk + tig]);
                bf[ni][1] = f2tf32(Bt[c * SA + kk + tig + 4]);
            }
#pragma unroll
            for (int mi = 0; mi < 4; mi++)
#pragma unroll
                for (int ni = 0; ni < 4; ni++)
                    mma_tf32(acc[mi][ni], af[mi], bf[ni]);
        }
        __syncthreads();
    }
}

// ---------------------------------------------------------------------------
// Kernel 1: QKV projection + RoPE + scatter to [B,H,S,HD]
// grid = (DD/128, MM/128, 3)
// ---------------------------------------------------------------------------
__global__ __launch_bounds__(256) void qkv_rope_mma_kernel(
    const float* __restrict__ X,
    const float* __restrict__ wq, const float* __restrict__ wk,
    const float* __restrict__ wv,
    const float* __restrict__ sinb, const float* __restrict__ cosb)
{
    __shared__ float As[2 * GEMM_SMEM_FLOATS];
    __shared__ float Bs[2 * GEMM_SMEM_FLOATS];

    const int m0 = blockIdx.y << 7;
    const int n0 = blockIdx.x << 7;
    const float* W = (blockIdx.z == 0) ? wq : (blockIdx.z == 1 ? wk : wv);
    float* outp    = (blockIdx.z == 0) ? g_q : (blockIdx.z == 1 ? g_k : g_v);

    float acc[4][4][4];
    gemm_mainloop_mma(acc, X, W, m0, n0, As, Bs);

    const int tid = threadIdx.x, wid = tid >> 5, lane = tid & 31;
    const int wm = wid & 1, wn = wid >> 1;
    const int gid = lane >> 2, tig = lane & 3;

#pragma unroll
    for (int mi = 0; mi < 4; mi++) {
#pragma unroll
        for (int half = 0; half < 2; half++) {
            int m  = m0 + wm * 64 + mi * 16 + gid + half * 8;
            int bb = m >> 11;
            int s  = m & (SS - 1);
#pragma unroll
            for (int ni = 0; ni < 4; ni++) {
                int n  = n0 + wn * 32 + ni * 8 + 2 * tig;   // even col
                int h  = n >> 6;
                int hd = n & 63;
                int ir = hd >> 1;
                float sn = sinb[s * (HDIM / 2) + ir];
                float cs = cosb[s * (HDIM / 2) + ir];
                float x1 = acc[mi][ni][half * 2 + 0];
                float x2 = acc[mi][ni][half * 2 + 1];
                size_t base = ((size_t)(bb * HH + h) * SS + s) * HDIM + hd;
                float2 o = make_float2(x1 * cs - x2 * sn, x2 * cs + x1 * sn);
                *reinterpret_cast<float2*>(&outp[base]) = o;
            }
        }
    }
}

// ---------------------------------------------------------------------------
// Kernel 3: O-proj + bias + residual -> g_x.  grid = (DD/128, MM/128)
// ---------------------------------------------------------------------------
__global__ __launch_bounds__(256) void oproj_mma_kernel(
    const float* __restrict__ hidden,
    const float* __restrict__ wo, const float* __restrict__ bo)
{
    __shared__ float As[2 * GEMM_SMEM_FLOATS];
    __shared__ float Bs[2 * GEMM_SMEM_FLOATS];

    const int m0 = blockIdx.y << 7;
    const int n0 = blockIdx.x << 7;

    float acc[4][4][4];
    gemm_mainloop_mma(acc, g_ctx, wo, m0, n0, As, Bs);

    const int tid = threadIdx.x, wid = tid >> 5, lane = tid & 31;
    const int wm = wid & 1, wn = wid >> 1;
    const int gid = lane >> 2, tig = lane & 3;

#pragma unroll
    for (int mi = 0; mi < 4; mi++) {
#pragma unroll
        for (int half = 0; half < 2; half++) {
            int m = m0 + wm * 64 + mi * 16 + gid + half * 8;
#pragma unroll
            for (int ni = 0; ni < 4; ni++) {
                int n = n0 + wn * 32 + ni * 8 + 2 * tig;
                float2 hv = *reinterpret_cast<const float2*>(&hidden[(size_t)m * DD + n]);
                float2 bv = *reinterpret_cast<const float2*>(&bo[n]);
                float2 o;
                o.x = acc[mi][ni][half * 2 + 0] + bv.x + hv.x;
                o.y = acc[mi][ni][half * 2 + 1] + bv.y + hv.y;
                *reinterpret_cast<float2*>(&g_x[(size_t)m * DD + n]) = o;
            }
        }
    }
}

// ---------------------------------------------------------------------------
// Kernel 2: flash attention with tf32 mma.
// Block: one (b,h), 128 query rows, 256 thr = 8 warps; warp owns 16 q rows.
// Key tiles of 64. K smem stride 68, V stride 72 (conflict-free frags),
// P per-warp smem patch stride 68.
// ---------------------------------------------------------------------------
#define KSTR 68
#define VSTR 72
#define PSTR2 68
#define AT_KOFF 0
#define AT_VOFF (64 * KSTR)                       // 4352
#define AT_POFF (AT_VOFF + 64 * VSTR)             // 8960
#define AT_FLOATS (AT_POFF + 8 * 16 * PSTR2)      // 8960 + 8704 = 17664
#define ATTN_SMEM_B (AT_FLOATS * 4)               // 70656 bytes

__global__ __launch_bounds__(256) void attn_mma_kernel()
{
    extern __shared__ float sm[];
    const int tid = threadIdx.x, wid = tid >> 5, lane = tid & 31;
    const int gid = lane >> 2, tig = lane & 3;
    const int q0 = blockIdx.x << 7;
    const int bh = blockIdx.y;
    const float* qp = g_q + (size_t)bh * SS * HDIM;
    const float* kp = g_k + (size_t)bh * SS * HDIM;
    const float* vp = g_v + (size_t)bh * SS * HDIM;

    // stage Q tile [128][64] into P region, then pull fragments to registers
#pragma unroll
    for (int r = 0; r < 8; r++) {
        int idx = tid + (r << 8);             // 0..2047
        int row = idx >> 4, c4 = idx & 15;
        float4 v = *reinterpret_cast<const float4*>(&qp[(size_t)(q0 + row) * HDIM + c4 * 4]);
        *reinterpret_cast<float4*>(&sm[AT_POFF + row * PSTR2 + c4 * 4]) = v;
    }
    __syncthreads();

    uint32_t qf[8][4];
    {
        int r = wid * 16 + gid;
#pragma unroll
        for (int kk = 0; kk < 8; kk++) {
            qf[kk][0] = f2tf32(sm[AT_POFF + r * PSTR2 + kk * 8 + tig]);
            qf[kk][1] = f2tf32(sm[AT_POFF + (r + 8) * PSTR2 + kk * 8 + tig]);
            qf[kk][2] = f2tf32(sm[AT_POFF + r * PSTR2 + kk * 8 + tig + 4]);
            qf[kk][3] = f2tf32(sm[AT_POFF + (r + 8) * PSTR2 + kk * 8 + tig + 4]);
        }
    }
    __syncthreads();

    float oacc[8][4];
#pragma unroll
    for (int ni = 0; ni < 8; ni++)
#pragma unroll
        for (int c = 0; c < 4; c++) oacc[ni][c] = 0.f;
    float mrow[2] = {-1e30f, -1e30f};
    float lrow[2] = {0.f, 0.f};

    for (int kt = 0; kt < SS; kt += 64) {
        // load K,V tiles
#pragma unroll
        for (int r = 0; r < 4; r++) {
            int idx = tid + (r << 8);        // 0..1023
            int row = idx >> 4, c4 = idx & 15;
            float4 kv = *reinterpret_cast<const float4*>(&kp[(size_t)(kt + row) * HDIM + c4 * 4]);
            float4 vv = *reinterpret_cast<const float4*>(&vp[(size_t)(kt + row) * HDIM + c4 * 4]);
            *reinterpret_cast<float4*>(&sm[AT_KOFF + row * KSTR + c4 * 4]) = kv;
            *reinterpret_cast<float4*>(&sm[AT_VOFF + row * VSTR + c4 * 4]) = vv;
        }
        __syncthreads();

        // S = Q K^T  (per warp: 16 x 64)
        float sacc[8][4];
#pragma unroll
        for (int ni = 0; ni < 8; ni++)
#pragma unroll
            for (int c = 0; c < 4; c++) sacc[ni][c] = 0.f;

#pragma unroll
        for (int ni = 0; ni < 8; ni++) {
            int key = ni * 8 + gid;
#pragma unroll
            for (int kk = 0; kk < 8; kk++) {
                uint32_t bfr[2];
                bfr[0] = f2tf32(sm[AT_KOFF + key * KSTR + kk * 8 + tig]);
                bfr[1] = f2tf32(sm[AT_KOFF + key * KSTR + kk * 8 + tig + 4]);
                mma_tf32(sacc[ni], qf[kk], bfr);
            }
        }

        // online softmax (rows gid and gid+8 of this warp's 16)
        const float SCL = 0.125f;
        float mx0 = -1e30f, mx1 = -1e30f;
#pragma unroll
        for (int ni = 0; ni < 8; ni++) {
            sacc[ni][0] *= SCL; sacc[ni][1] *= SCL;
            sacc[ni][2] *= SCL; sacc[ni][3] *= SCL;
            mx0 = fmaxf(mx0, fmaxf(sacc[ni][0], sacc[ni][1]));
            mx1 = fmaxf(mx1, fmaxf(sacc[ni][2], sacc[ni][3]));
        }
#pragma unroll
        for (int off = 1; off <= 2; off <<= 1) {
            mx0 = fmaxf(mx0, __shfl_xor_sync(0xffffffffu, mx0, off));
            mx1 = fmaxf(mx1, __shfl_xor_sync(0xffffffffu, mx1, off));
        }
        float mn0 = fmaxf(mrow[0], mx0), mn1 = fmaxf(mrow[1], mx1);
        float corr0 = __expf(mrow[0] - mn0), corr1 = __expf(mrow[1] - mn1);
        float rs0 = 0.f, rs1 = 0.f;
        float* Pw = sm + AT_POFF + wid * 16 * PSTR2;
#pragma unroll
        for (int ni = 0; ni < 8; ni++) {
            float p0 = __expf(sacc[ni][0] - mn0);
            float p1 = __expf(sacc[ni][1] - mn0);
            float p2 = __expf(sacc[ni][2] - mn1);
            float p3 = __expf(sacc[ni][3] - mn1);
            rs0 += p0 + p1; rs1 += p2 + p3;
            int c = ni * 8 + 2 * tig;
            *reinterpret_cast<float2*>(&Pw[gid * PSTR2 + c])       = make_float2(p0, p1);
            *reinterpret_cast<float2*>(&Pw[(gid + 8) * PSTR2 + c]) = make_float2(p2, p3);
        }
#pragma unroll
        for (int off = 1; off <= 2; off <<= 1) {
            rs0 += __shfl_xor_sync(0xffffffffu, rs0, off);
            rs1 += __shfl_xor_sync(0xffffffffu, rs1, off);
        }
        lrow[0] = lrow[0] * corr0 + rs0;
        lrow[1] = lrow[1] * corr1 + rs1;
        mrow[0] = mn0; mrow[1] = mn1;
#pragma unroll
        for (int ni = 0; ni < 8; ni++) {
            oacc[ni][0] *= corr0; oacc[ni][1] *= corr0;
            oacc[ni][2] *= corr1; oacc[ni][3] *= corr1;
        }
        __syncwarp();

        // O += P V   (per warp: 16 x 64, k = 64 keys)
#pragma unroll
        for (int kk = 0; kk < 8; kk++) {
            uint32_t pf[4];
            pf[0] = f2tf32(Pw[gid * PSTR2 + kk * 8 + tig]);
            pf[1] = f2tf32(Pw[(gid + 8) * PSTR2 + kk * 8 + tig]);
            pf[2] = f2tf32(Pw[gid * PSTR2 + kk * 8 + tig + 4]);
            pf[3] = f2tf32(Pw[(gid + 8) * PSTR2 + kk * 8 + tig + 4]);
#pragma unroll
            for (int ni = 0; ni < 8; ni++) {
                uint32_t vf[2];
                vf[0] = f2tf32(sm[AT_VOFF + (kk * 8 + tig) * VSTR + ni * 8 + gid]);
                vf[1] = f2tf32(sm[AT_VOFF + (kk * 8 + tig + 4) * VSTR + ni * 8 + gid]);
                mma_tf32(oacc[ni], pf, vf);
            }
        }
        __syncthreads();
    }

    // write ctx [B,S,D]
    const int bb = bh >> 4;
    const int h  = bh & 15;
    float inv0 = 1.0f / lrow[0];
    float inv1 = 1.0f / lrow[1];
    int s0 = q0 + wid * 16 + gid;
#pragma unroll
    for (int ni = 0; ni < 8; ni++) {
        int d = ni * 8 + 2 * tig;
        size_t base0 = ((size_t)bb * SS + s0) * DD + h * HDIM + d;
        size_t base1 = ((size_t)bb * SS + s0 + 8) * DD + h * HDIM + d;
        *reinterpret_cast<float2*>(&g_ctx[base0]) =
            make_float2(oacc[ni][0] * inv0, oacc[ni][1] * inv0);
        *reinterpret_cast<float2*>(&g_ctx[base1]) =
            make_float2(oacc[ni][2] * inv1, oacc[ni][3] * inv1);
    }
}

// ---------------------------------------------------------------------------
// Kernel 4: RMS norm per row of g_x
// ---------------------------------------------------------------------------
__global__ __launch_bounds__(256) void rmsnorm_kernel(
    const float* __restrict__ scale, float* __restrict__ out)
{
    __shared__ float red[8];
    __shared__ float s_tot;
    const int row = blockIdx.x;
    const int tid = threadIdx.x;
    const float4* xr = reinterpret_cast<const float4*>(g_x + (size_t)row * DD);
    float4 xv = xr[tid];
    float ss = xv.x*xv.x + xv.y*xv.y + xv.z*xv.z + xv.w*xv.w;
#pragma unroll
    for (int off = 16; off > 0; off >>= 1)
        ss += __shfl_xor_sync(0xffffffffu, ss, off);
    if ((tid & 31) == 0) red[tid >> 5] = ss;
    __syncthreads();
    if (tid == 0) {
        float t = 0.f;
#pragma unroll
        for (int w = 0; w < 8; w++) t += red[w];
        s_tot = t;
    }
    __syncthreads();
    float rms = sqrtf(s_tot * (1.0f / DD));
    float inv = 1.0f / (rms + RMS_EPS);
    float4 sc = reinterpret_cast<const float4*>(scale)[tid];
    float4 ov;
    ov.x = xv.x * sc.x * inv;
    ov.y = xv.y * sc.y * inv;
    ov.z = xv.z * sc.z * inv;
    ov.w = xv.w * sc.w * inv;
    reinterpret_cast<float4*>(out)[(size_t)row * (DD / 4) + tid] = ov;
}

// ---------------------------------------------------------------------------
extern "C" void kernel_launch(void* const* d_in, const int* in_sizes, int n_in,
                              void* d_out, int out_size)
{
    const float* hidden = (const float*)d_in[0];
    const float* sinb   = (const float*)d_in[1];
    const float* cosb   = (const float*)d_in[2];
    const float* wq     = (const float*)d_in[3];
    const float* wk     = (const float*)d_in[4];
    const float* wv     = (const float*)d_in[5];
    const float* wo     = (const float*)d_in[6];
    const float* bo     = (const float*)d_in[7];
    const float* scale  = (const float*)d_in[8];
    float* out = (float*)d_out;

    cudaFuncSetAttribute(attn_mma_kernel,
                         cudaFuncAttributeMaxDynamicSharedMemorySize, ATTN_SMEM_B);

    qkv_rope_mma_kernel<<<dim3(DD / 128, MM / 128, 3), 256>>>(hidden, wq, wk, wv, sinb, cosb);
    attn_mma_kernel<<<dim3(SS / 128, BB * HH), 256, ATTN_SMEM_B>>>();
    oproj_mma_kernel<<<dim3(DD / 128, MM / 128), 256>>>(hidden, wo, bo);
    rmsnorm_kernel<<<MM, 256>>>(scale, out);
}

// round 5
// speedup vs baseline: 5.8682x; 2.1480x over previous
#include <cuda_runtime.h>
#include <cuda_bf16.h>
#include <math.h>
#include <stdint.h>

// Problem constants
#define BB   2
#define SS   2048
#define DD   1024
#define HH   16
#define HDIM 64
#define MM   (BB*SS)          // 4096 rows
#define RMS_EPS 1e-8f

// Scratch
__device__ __nv_bfloat16 g_xb[MM*DD];          // hidden in bf16
__device__ __nv_bfloat16 g_wqb[DD*DD];
__device__ __nv_bfloat16 g_wkb[DD*DD];
__device__ __nv_bfloat16 g_wvb[DD*DD];
__device__ __nv_bfloat16 g_wob[DD*DD];
__device__ __nv_bfloat16 g_qb[BB*HH*SS*HDIM];  // [B,H,S,HD], pre-scaled by 1/8
__device__ __nv_bfloat16 g_kb[BB*HH*SS*HDIM];  // [B,H,S,HD]
__device__ __nv_bfloat16 g_vtb[BB*HH*HDIM*SS]; // [B,H,HD,S]  (transposed V)
__device__ __nv_bfloat16 g_ctxb[MM*DD];        // [B,S,D]
__device__ float g_x[MM*DD];                   // post-proj + residual (fp32)

// ---------------------------------------------------------------------------
// helpers
// ---------------------------------------------------------------------------
__device__ __forceinline__ uint32_t smem_u32(const void* p) {
    uint32_t a;
    asm("{ .reg .u64 t; cvta.to.shared.u64 t, %1; cvt.u32.u64 %0, t; }"
        : "=r"(a) : "l"(p));
    return a;
}

// D += A(16x16) * B(16x8), bf16 inputs, fp32 accum
__device__ __forceinline__ void mma_bf16(float* d, const uint32_t* a, const uint32_t* b) {
    asm volatile(
        "mma.sync.aligned.m16n8k16.row.col.f32.bf16.bf16.f32 "
        "{%0,%1,%2,%3}, {%4,%5,%6,%7}, {%8,%9}, {%0,%1,%2,%3};"
        : "+f"(d[0]), "+f"(d[1]), "+f"(d[2]), "+f"(d[3])
        : "r"(a[0]), "r"(a[1]), "r"(a[2]), "r"(a[3]), "r"(b[0]), "r"(b[1]));
}

#define CP_ASYNC16(saddr, gptr) \
    asm volatile("cp.async.cg.shared.global [%0], [%1], 16;" :: "r"(saddr), "l"(gptr))
#define CP_COMMIT() asm volatile("cp.async.commit_group;")
#define CP_WAIT(N)  asm volatile("cp.async.wait_group %0;" :: "n"(N))

__device__ __forceinline__ uint32_t pack_bf16(float x, float y) {
    __nv_bfloat162 p = __floats2bfloat162_rn(x, y);
    return *reinterpret_cast<uint32_t*>(&p);
}

// ---------------------------------------------------------------------------
// Kernel 0: fp32 -> bf16 conversion prepass
// ---------------------------------------------------------------------------
__global__ __launch_bounds__(256) void cvt_bf16_kernel(
    const float4* __restrict__ src, uint2* __restrict__ dst, int n4)
{
    int i = blockIdx.x * 256 + threadIdx.x;
    if (i < n4) {
        float4 v = src[i];
        uint2 o;
        o.x = pack_bf16(v.x, v.y);
        o.y = pack_bf16(v.z, v.w);
        dst[i] = o;
    }
}

// ---------------------------------------------------------------------------
// bf16 GEMM mainloop: 128x128 tile of A[M,1024] @ W[1024,1024]^T
// 256 threads = 8 warps (2x4), warp tile 64x32, KC=32 bf16, double buffer.
// ---------------------------------------------------------------------------
#define KCB   32
#define SAB   40                       // smem row stride (bf16) = 80B
#define TILEB (128 * SAB)              // bf16 per buffer

__device__ __forceinline__ void gemm_mainloop_bf16(
    float (&acc)[4][4][4],
    const __nv_bfloat16* __restrict__ A, const __nv_bfloat16* __restrict__ W,
    int m0, int n0, __nv_bfloat16* As, __nv_bfloat16* Bs)
{
    const int tid  = threadIdx.x;
    const int wid  = tid >> 5, lane = tid & 31;
    const int wm = wid & 1, wn = wid >> 1;
    const int gid = lane >> 2, tig = lane & 3;

    const uint32_t as_base = smem_u32(As);
    const uint32_t bs_base = smem_u32(Bs);

#pragma unroll
    for (int mi = 0; mi < 4; mi++)
#pragma unroll
        for (int ni = 0; ni < 4; ni++)
#pragma unroll
            for (int c = 0; c < 4; c++) acc[mi][ni][c] = 0.f;

    auto issue = [&](int buf, int k0) {
#pragma unroll
        for (int r = 0; r < 2; r++) {
            int idx = tid + (r << 8);      // 0..511
            int row = idx >> 2, c = idx & 3;
            uint32_t soff = (uint32_t)((buf * TILEB + row * SAB) * 2 + c * 16);
            const char* ga = (const char*)(A + (size_t)(m0 + row) * DD + k0) + c * 16;
            const char* gb = (const char*)(W + (size_t)(n0 + row) * DD + k0) + c * 16;
            CP_ASYNC16(as_base + soff, ga);
            CP_ASYNC16(bs_base + soff, gb);
        }
        CP_COMMIT();
    };

    issue(0, 0);
    for (int k0 = 0; k0 < DD; k0 += KCB) {
        int buf = (k0 / KCB) & 1;
        bool has_next = (k0 + KCB) < DD;
        if (has_next) {
            issue(buf ^ 1, k0 + KCB);
            CP_WAIT(1);
        } else {
            CP_WAIT(0);
        }
        __syncthreads();

        const __nv_bfloat16* At = As + buf * TILEB;
        const __nv_bfloat16* Bt = Bs + buf * TILEB;
#pragma unroll
        for (int ks = 0; ks < KCB; ks += 16) {
            uint32_t af[4][4], bf[4][2];
#pragma unroll
            for (int mi = 0; mi < 4; mi++) {
                int r = wm * 64 + mi * 16 + gid;
                af[mi][0] = *(const uint32_t*)(At + r * SAB + ks + 2 * tig);
                af[mi][1] = *(const uint32_t*)(At + (r + 8) * SAB + ks + 2 * tig);
                af[mi][2] = *(const uint32_t*)(At + r * SAB + ks + 8 + 2 * tig);
                af[mi][3] = *(const uint32_t*)(At + (r + 8) * SAB + ks + 8 + 2 * tig);
            }
#pragma unroll
            for (int ni = 0; ni < 4; ni++) {
                int c = wn * 32 + ni * 8 + gid;
                bf[ni][0] = *(const uint32_t*)(Bt + c * SAB + ks + 2 * tig);
                bf[ni][1] = *(const uint32_t*)(Bt + c * SAB + ks + 8 + 2 * tig);
            }
#pragma unroll
            for (int mi = 0; mi < 4; mi++)
#pragma unroll
                for (int ni = 0; ni < 4; ni++)
                    mma_bf16(acc[mi][ni], af[mi], bf[ni]);
        }
        __syncthreads();
    }
}

// ---------------------------------------------------------------------------
// Kernel 1: QKV projection (bf16 mma) + RoPE + scatter
//   z=0: q (scaled by 0.125) -> g_qb [B,H,S,HD]
//   z=1: k -> g_kb [B,H,S,HD]
//   z=2: v -> g_vtb [B,H,HD,S]  (transposed)
// grid = (DD/128, MM/128, 3)
// ---------------------------------------------------------------------------
__global__ __launch_bounds__(256) void qkv_rope_mma_kernel(
    const float* __restrict__ sinb, const float* __restrict__ cosb)
{
    __shared__ __nv_bfloat16 As[2 * TILEB];
    __shared__ __nv_bfloat16 Bs[2 * TILEB];

    const int m0 = blockIdx.y << 7;
    const int n0 = blockIdx.x << 7;
    const int z  = blockIdx.z;
    const __nv_bfloat16* W = (z == 0) ? g_wqb : (z == 1 ? g_wkb : g_wvb);

    float acc[4][4][4];
    gemm_mainloop_bf16(acc, g_xb, W, m0, n0, As, Bs);

    const int tid = threadIdx.x, wid = tid >> 5, lane = tid & 31;
    const int wm = wid & 1, wn = wid >> 1;
    const int gid = lane >> 2, tig = lane & 3;
    const float qs = (z == 0) ? 0.125f : 1.0f;

#pragma unroll
    for (int mi = 0; mi < 4; mi++) {
#pragma unroll
        for (int half = 0; half < 2; half++) {
            int m  = m0 + wm * 64 + mi * 16 + gid + half * 8;
            int bb = m >> 11;
            int s  = m & (SS - 1);
#pragma unroll
            for (int ni = 0; ni < 4; ni++) {
                int n  = n0 + wn * 32 + ni * 8 + 2 * tig;   // even col
                int h  = n >> 6;
                int hd = n & 63;
                int ir = hd >> 1;
                float sn = sinb[s * (HDIM / 2) + ir];
                float cs = cosb[s * (HDIM / 2) + ir];
                float x1 = acc[mi][ni][half * 2 + 0];
                float x2 = acc[mi][ni][half * 2 + 1];
                float o1 = (x1 * cs - x2 * sn) * qs;
                float o2 = (x2 * cs + x1 * sn) * qs;
                if (z < 2) {
                    __nv_bfloat16* outp = (z == 0) ? g_qb : g_kb;
                    size_t base = ((size_t)(bb * HH + h) * SS + s) * HDIM + hd;
                    *reinterpret_cast<uint32_t*>(&outp[base]) = pack_bf16(o1, o2);
                } else {
                    size_t base = ((size_t)(bb * HH + h) * HDIM + hd) * SS + s;
                    g_vtb[base]      = __float2bfloat16_rn(o1);
                    g_vtb[base + SS] = __float2bfloat16_rn(o2);
                }
            }
        }
    }
}

// ---------------------------------------------------------------------------
// Kernel 3: O-proj (bf16 mma) + bias + residual -> g_x (fp32)
// ---------------------------------------------------------------------------
__global__ __launch_bounds__(256) void oproj_mma_kernel(
    const float* __restrict__ hidden, const float* __restrict__ bo)
{
    __shared__ __nv_bfloat16 As[2 * TILEB];
    __shared__ __nv_bfloat16 Bs[2 * TILEB];

    const int m0 = blockIdx.y << 7;
    const int n0 = blockIdx.x << 7;

    float acc[4][4][4];
    gemm_mainloop_bf16(acc, g_ctxb, g_wob, m0, n0, As, Bs);

    const int tid = threadIdx.x, wid = tid >> 5, lane = tid & 31;
    const int wm = wid & 1, wn = wid >> 1;
    const int gid = lane >> 2, tig = lane & 3;

#pragma unroll
    for (int mi = 0; mi < 4; mi++) {
#pragma unroll
        for (int half = 0; half < 2; half++) {
            int m = m0 + wm * 64 + mi * 16 + gid + half * 8;
#pragma unroll
            for (int ni = 0; ni < 4; ni++) {
                int n = n0 + wn * 32 + ni * 8 + 2 * tig;
                float2 hv = *reinterpret_cast<const float2*>(&hidden[(size_t)m * DD + n]);
                float2 bv = *reinterpret_cast<const float2*>(&bo[n]);
                float2 o;
                o.x = acc[mi][ni][half * 2 + 0] + bv.x + hv.x;
                o.y = acc[mi][ni][half * 2 + 1] + bv.y + hv.y;
                *reinterpret_cast<float2*>(&g_x[(size_t)m * DD + n]) = o;
            }
        }
    }
}

// ---------------------------------------------------------------------------
// Kernel 2: flash attention, all-bf16 fragments, fp32 softmax/accum.
// Block: one (b,h) x 128 q rows; 8 warps x 16 rows. Key tiles of 64.
// smem: Ks[64][72], VsT[64][72] (dim-major), Pw/Qs[128][72], all bf16.
// ---------------------------------------------------------------------------
#define KSTRB 72
__global__ __launch_bounds__(256) void attn_mma_kernel()
{
    __shared__ __nv_bfloat16 Ks [64][KSTRB];
    __shared__ __nv_bfloat16 VsT[64][KSTRB];
    __shared__ __nv_bfloat16 Pw [128][KSTRB];   // also Q staging

    const int tid = threadIdx.x, wid = tid >> 5, lane = tid & 31;
    const int gid = lane >> 2, tig = lane & 3;
    const int q0 = blockIdx.x << 7;
    const int bh = blockIdx.y;
    const __nv_bfloat16* qp = g_qb  + (size_t)bh * SS * HDIM;
    const __nv_bfloat16* kp = g_kb  + (size_t)bh * SS * HDIM;
    const __nv_bfloat16* vp = g_vtb + (size_t)bh * HDIM * SS;

    // stage Q tile [128][64] bf16
#pragma unroll
    for (int r = 0; r < 4; r++) {
        int idx = tid + (r << 8);             // 0..1023 chunks of 8 bf16
        int row = idx >> 3, c = idx & 7;
        *reinterpret_cast<uint4*>(&Pw[row][c * 8]) =
            *reinterpret_cast<const uint4*>(&qp[(size_t)(q0 + row) * HDIM + c * 8]);
    }
    __syncthreads();

    uint32_t qf[4][4];
    {
        int r = wid * 16 + gid;
#pragma unroll
        for (int kk = 0; kk < 4; kk++) {
            qf[kk][0] = *(const uint32_t*)(&Pw[r][kk * 16 + 2 * tig]);
            qf[kk][1] = *(const uint32_t*)(&Pw[r + 8][kk * 16 + 2 * tig]);
            qf[kk][2] = *(const uint32_t*)(&Pw[r][kk * 16 + 8 + 2 * tig]);
            qf[kk][3] = *(const uint32_t*)(&Pw[r + 8][kk * 16 + 8 + 2 * tig]);
        }
    }

    float oacc[8][4];
#pragma unroll
    for (int ni = 0; ni < 8; ni++)
#pragma unroll
        for (int c = 0; c < 4; c++) oacc[ni][c] = 0.f;
    float mrow[2] = {-1e30f, -1e30f};
    float lrow[2] = {0.f, 0.f};

    for (int kt = 0; kt < SS; kt += 64) {
        // load K tile [key][dim] and V^T tile [dim][key]
#pragma unroll
        for (int r = 0; r < 2; r++) {
            int idx = tid + (r << 8);        // 0..511
            int row = idx >> 3, c = idx & 7;
            *reinterpret_cast<uint4*>(&Ks[row][c * 8]) =
                *reinterpret_cast<const uint4*>(&kp[(size_t)(kt + row) * HDIM + c * 8]);
            *reinterpret_cast<uint4*>(&VsT[row][c * 8]) =
                *reinterpret_cast<const uint4*>(&vp[(size_t)row * SS + kt + c * 8]);
        }
        __syncthreads();

        // S = Q K^T  (per warp: 16 x 64), q pre-scaled
        float sacc[8][4];
#pragma unroll
        for (int ni = 0; ni < 8; ni++)
#pragma unroll
            for (int c = 0; c < 4; c++) sacc[ni][c] = 0.f;

#pragma unroll
        for (int ni = 0; ni < 8; ni++) {
            int key = ni * 8 + gid;
#pragma unroll
            for (int kk = 0; kk < 4; kk++) {
                uint32_t bfr[2];
                bfr[0] = *(const uint32_t*)(&Ks[key][kk * 16 + 2 * tig]);
                bfr[1] = *(const uint32_t*)(&Ks[key][kk * 16 + 8 + 2 * tig]);
                mma_bf16(sacc[ni], qf[kk], bfr);
            }
        }

        // online softmax (rows gid and gid+8 of this warp's 16)
        float mx0 = -1e30f, mx1 = -1e30f;
#pragma unroll
        for (int ni = 0; ni < 8; ni++) {
            mx0 = fmaxf(mx0, fmaxf(sacc[ni][0], sacc[ni][1]));
            mx1 = fmaxf(mx1, fmaxf(sacc[ni][2], sacc[ni][3]));
        }
#pragma unroll
        for (int off = 1; off <= 2; off <<= 1) {
            mx0 = fmaxf(mx0, __shfl_xor_sync(0xffffffffu, mx0, off));
            mx1 = fmaxf(mx1, __shfl_xor_sync(0xffffffffu, mx1, off));
        }
        float mn0 = fmaxf(mrow[0], mx0), mn1 = fmaxf(mrow[1], mx1);
        float corr0 = __expf(mrow[0] - mn0), corr1 = __expf(mrow[1] - mn1);
        float rs0 = 0.f, rs1 = 0.f;
        __nv_bfloat16* Pq = &Pw[wid * 16][0];
#pragma unroll
        for (int ni = 0; ni < 8; ni++) {
            float p0 = __expf(sacc[ni][0] - mn0);
            float p1 = __expf(sacc[ni][1] - mn0);
            float p2 = __expf(sacc[ni][2] - mn1);
            float p3 = __expf(sacc[ni][3] - mn1);
            rs0 += p0 + p1; rs1 += p2 + p3;
            int c = ni * 8 + 2 * tig;
            *reinterpret_cast<uint32_t*>(Pq + gid * KSTRB + c)       = pack_bf16(p0, p1);
            *reinterpret_cast<uint32_t*>(Pq + (gid + 8) * KSTRB + c) = pack_bf16(p2, p3);
        }
#pragma unroll
        for (int off = 1; off <= 2; off <<= 1) {
            rs0 += __shfl_xor_sync(0xffffffffu, rs0, off);
            rs1 += __shfl_xor_sync(0xffffffffu, rs1, off);
        }
        lrow[0] = lrow[0] * corr0 + rs0;
        lrow[1] = lrow[1] * corr1 + rs1;
        mrow[0] = mn0; mrow[1] = mn1;
#pragma unroll
        for (int ni = 0; ni < 8; ni++) {
            oacc[ni][0] *= corr0; oacc[ni][1] *= corr0;
            oacc[ni][2] *= corr1; oacc[ni][3] *= corr1;
        }
        __syncwarp();

        // O += P V   (per warp: 16 q x 64 dims, k = 64 keys)
#pragma unroll
        for (int kk = 0; kk < 4; kk++) {
            uint32_t pf[4];
            pf[0] = *(const uint32_t*)(Pq + gid * KSTRB + kk * 16 + 2 * tig);
            pf[1] = *(const uint32_t*)(Pq + (gid + 8) * KSTRB + kk * 16 + 2 * tig);
            pf[2] = *(const uint32_t*)(Pq + gid * KSTRB + kk * 16 + 8 + 2 * tig);
            pf[3] = *(const uint32_t*)(Pq + (gid + 8) * KSTRB + kk * 16 + 8 + 2 * tig);
#pragma unroll
            for (int ni = 0; ni < 8; ni++) {
                int dim = ni * 8 + gid;
                uint32_t vf[2];
                vf[0] = *(const uint32_t*)(&VsT[dim][kk * 16 + 2 * tig]);
                vf[1] = *(const uint32_t*)(&VsT[dim][kk * 16 + 8 + 2 * tig]);
                mma_bf16(oacc[ni], pf, vf);
            }
        }
        __syncthreads();
    }

    // write ctx [B,S,D] as bf16
    const int bb = bh >> 4;
    const int h  = bh & 15;
    float inv0 = 1.0f / lrow[0];
    float inv1 = 1.0f / lrow[1];
    int s0 = q0 + wid * 16 + gid;
#pragma unroll
    for (int ni = 0; ni < 8; ni++) {
        int d = ni * 8 + 2 * tig;
        size_t base0 = ((size_t)bb * SS + s0) * DD + h * HDIM + d;
        size_t base1 = ((size_t)bb * SS + s0 + 8) * DD + h * HDIM + d;
        *reinterpret_cast<uint32_t*>(&g_ctxb[base0]) =
            pack_bf16(oacc[ni][0] * inv0, oacc[ni][1] * inv0);
        *reinterpret_cast<uint32_t*>(&g_ctxb[base1]) =
            pack_bf16(oacc[ni][2] * inv1, oacc[ni][3] * inv1);
    }
}

// ---------------------------------------------------------------------------
// Kernel 4: RMS norm per row of g_x
// ---------------------------------------------------------------------------
__global__ __launch_bounds__(256) void rmsnorm_kernel(
    const float* __restrict__ scale, float* __restrict__ out)
{
    __shared__ float red[8];
    __shared__ float s_tot;
    const int row = blockIdx.x;
    const int tid = threadIdx.x;
    const float4* xr = reinterpret_cast<const float4*>(g_x + (size_t)row * DD);
    float4 xv = xr[tid];
    float ss = xv.x*xv.x + xv.y*xv.y + xv.z*xv.z + xv.w*xv.w;
#pragma unroll
    for (int off = 16; off > 0; off >>= 1)
        ss += __shfl_xor_sync(0xffffffffu, ss, off);
    if ((tid & 31) == 0) red[tid >> 5] = ss;
    __syncthreads();
    if (tid == 0) {
        float t = 0.f;
#pragma unroll
        for (int w = 0; w < 8; w++) t += red[w];
        s_tot = t;
    }
    __syncthreads();
    float rms = sqrtf(s_tot * (1.0f / DD));
    float inv = 1.0f / (rms + RMS_EPS);
    float4 sc = reinterpret_cast<const float4*>(scale)[tid];
    float4 ov;
    ov.x = xv.x * sc.x * inv;
    ov.y = xv.y * sc.y * inv;
    ov.z = xv.z * sc.z * inv;
    ov.w = xv.w * sc.w * inv;
    reinterpret_cast<float4*>(out)[(size_t)row * (DD / 4) + tid] = ov;
}

// ---------------------------------------------------------------------------
extern "C" void kernel_launch(void* const* d_in, const int* in_sizes, int n_in,
                              void* d_out, int out_size)
{
    const float* hidden = (const float*)d_in[0];
    const float* sinb   = (const float*)d_in[1];
    const float* cosb   = (const float*)d_in[2];
    const float* wq     = (const float*)d_in[3];
    const float* wk     = (const float*)d_in[4];
    const float* wv     = (const float*)d_in[5];
    const float* wo     = (const float*)d_in[6];
    const float* bo     = (const float*)d_in[7];
    const float* scale  = (const float*)d_in[8];
    float* out = (float*)d_out;

    // resolve device-global addresses (host side, graph-capturable)
    static void *p_xb = nullptr, *p_wqb, *p_wkb, *p_wvb, *p_wob;
    if (!p_xb) {
        cudaGetSymbolAddress(&p_xb,  g_xb);
        cudaGetSymbolAddress(&p_wqb, g_wqb);
        cudaGetSymbolAddress(&p_wkb, g_wkb);
        cudaGetSymbolAddress(&p_wvb, g_wvb);
        cudaGetSymbolAddress(&p_wob, g_wob);
    }

    const int n4h = MM * DD / 4;   // hidden float4 count
    const int n4w = DD * DD / 4;   // weight float4 count
    cvt_bf16_kernel<<<(n4h + 255) / 256, 256>>>((const float4*)hidden, (uint2*)p_xb,  n4h);
    cvt_bf16_kernel<<<(n4w + 255) / 256, 256>>>((const float4*)wq,     (uint2*)p_wqb, n4w);
    cvt_bf16_kernel<<<(n4w + 255) / 256, 256>>>((const float4*)wk,     (uint2*)p_wkb, n4w);
    cvt_bf16_kernel<<<(n4w + 255) / 256, 256>>>((const float4*)wv,     (uint2*)p_wvb, n4w);
    cvt_bf16_kernel<<<(n4w + 255) / 256, 256>>>((const float4*)wo,     (uint2*)p_wob, n4w);

    qkv_rope_mma_kernel<<<dim3(DD / 128, MM / 128, 3), 256>>>(sinb, cosb);
    attn_mma_kernel<<<dim3(SS / 128, BB * HH), 256>>>();
    oproj_mma_kernel<<<dim3(DD / 128, MM / 128), 256>>>(hidden, bo);
    rmsnorm_kernel<<<MM, 256>>>(scale, out);
}

// round 6
// speedup vs baseline: 6.6604x; 1.1350x over previous
#include <cuda_runtime.h>
#include <cuda_bf16.h>
#include <math.h>
#include <stdint.h>

// Problem constants
#define BB   2
#define SS   2048
#define DD   1024
#define HH   16
#define HDIM 64
#define MM   (BB*SS)          // 4096 rows
#define RMS_EPS 1e-8f

// Scratch
__device__ __nv_bfloat16 g_xb[MM*DD];          // hidden in bf16
__device__ __nv_bfloat16 g_wqb[DD*DD];
__device__ __nv_bfloat16 g_wkb[DD*DD];
__device__ __nv_bfloat16 g_wvb[DD*DD];
__device__ __nv_bfloat16 g_wob[DD*DD];
__device__ __nv_bfloat16 g_qb[BB*HH*SS*HDIM];  // [B,H,S,HD], pre-scaled by 1/8
__device__ __nv_bfloat16 g_kb[BB*HH*SS*HDIM];  // [B,H,S,HD]
__device__ __nv_bfloat16 g_vtb[BB*HH*HDIM*SS]; // [B,H,HD,S]  (transposed V)
__device__ __nv_bfloat16 g_ctxb[MM*DD];        // [B,S,D]
__device__ float g_x[MM*DD];                   // post-proj + residual (fp32)

// ---------------------------------------------------------------------------
// helpers
// ---------------------------------------------------------------------------
__device__ __forceinline__ uint32_t smem_u32(const void* p) {
    uint32_t a;
    asm("{ .reg .u64 t; cvta.to.shared.u64 t, %1; cvt.u32.u64 %0, t; }"
        : "=r"(a) : "l"(p));
    return a;
}

// D += A(16x16) * B(16x8), bf16 inputs, fp32 accum
__device__ __forceinline__ void mma_bf16(float* d, const uint32_t* a, const uint32_t* b) {
    asm volatile(
        "mma.sync.aligned.m16n8k16.row.col.f32.bf16.bf16.f32 "
        "{%0,%1,%2,%3}, {%4,%5,%6,%7}, {%8,%9}, {%0,%1,%2,%3};"
        : "+f"(d[0]), "+f"(d[1]), "+f"(d[2]), "+f"(d[3])
        : "r"(a[0]), "r"(a[1]), "r"(a[2]), "r"(a[3]), "r"(b[0]), "r"(b[1]));
}

#define LDMX4(r0, r1, r2, r3, addr) \
    asm volatile("ldmatrix.sync.aligned.m8n8.x4.shared.b16 {%0,%1,%2,%3}, [%4];" \
                 : "=r"(r0), "=r"(r1), "=r"(r2), "=r"(r3) : "r"(addr))

#define CP_ASYNC16(saddr, gptr) \
    asm volatile("cp.async.cg.shared.global [%0], [%1], 16;" :: "r"(saddr), "l"(gptr))
#define CP_COMMIT() asm volatile("cp.async.commit_group;")
#define CP_WAIT(N)  asm volatile("cp.async.wait_group %0;" :: "n"(N))

__device__ __forceinline__ uint32_t pack_bf16(float x, float y) {
    __nv_bfloat162 p = __floats2bfloat162_rn(x, y);
    return *reinterpret_cast<uint32_t*>(&p);
}

// ---------------------------------------------------------------------------
// Kernel 0: fp32 -> bf16 conversion prepass (hidden; weights fused 2D)
// ---------------------------------------------------------------------------
__global__ __launch_bounds__(256) void cvt_h_kernel(const float4* __restrict__ src)
{
    int i = blockIdx.x * 256 + threadIdx.x;
    if (i < MM * DD / 4) {
        float4 v = src[i];
        uint2 o;
        o.x = pack_bf16(v.x, v.y);
        o.y = pack_bf16(v.z, v.w);
        reinterpret_cast<uint2*>(g_xb)[i] = o;
    }
}

__global__ __launch_bounds__(256) void cvt_w_kernel(
    const float4* __restrict__ wq, const float4* __restrict__ wk,
    const float4* __restrict__ wv, const float4* __restrict__ wo)
{
    int i = blockIdx.x * 256 + threadIdx.x;
    if (i >= DD * DD / 4) return;
    int z = blockIdx.y;
    const float4* s = (z == 0) ? wq : (z == 1) ? wk : (z == 2) ? wv : wo;
    __nv_bfloat16* dp = (z == 0) ? g_wqb : (z == 1) ? g_wkb : (z == 2) ? g_wvb : g_wob;
    float4 v = s[i];
    uint2 o;
    o.x = pack_bf16(v.x, v.y);
    o.y = pack_bf16(v.z, v.w);
    reinterpret_cast<uint2*>(dp)[i] = o;
}

// ---------------------------------------------------------------------------
// bf16 GEMM mainloop: 128x128 tile of A[M,1024] @ W[1024,1024]^T
// 256 threads = 8 warps (2x4), warp tile 64x32, KC=32 bf16, double buffer,
// ldmatrix fragment loads.
// ---------------------------------------------------------------------------
#define KCB   32
#define SAB   40                       // smem row stride (bf16) = 80B
#define TILEB (128 * SAB)              // bf16 per buffer

__device__ __forceinline__ void gemm_mainloop_bf16(
    float (&acc)[4][4][4],
    const __nv_bfloat16* __restrict__ A, const __nv_bfloat16* __restrict__ W,
    int m0, int n0, __nv_bfloat16* As, __nv_bfloat16* Bs)
{
    const int tid  = threadIdx.x;
    const int wid  = tid >> 5, lane = tid & 31;
    const int wm = wid & 1, wn = wid >> 1;

    const uint32_t as_base = smem_u32(As);
    const uint32_t bs_base = smem_u32(Bs);

    // per-lane ldmatrix byte offsets
    uint32_t a_off[4], b_off[2];
#pragma unroll
    for (int mi = 0; mi < 4; mi++)
        a_off[mi] = (uint32_t)(((wm * 64 + mi * 16 + (lane & 15)) * SAB + (lane >> 4) * 8) * 2);
#pragma unroll
    for (int nip = 0; nip < 2; nip++)
        b_off[nip] = (uint32_t)(((wn * 32 + nip * 16 + (lane & 7) + ((lane >> 4) & 1) * 8) * SAB
                                 + ((lane >> 3) & 1) * 8) * 2);

#pragma unroll
    for (int mi = 0; mi < 4; mi++)
#pragma unroll
        for (int ni = 0; ni < 4; ni++)
#pragma unroll
            for (int c = 0; c < 4; c++) acc[mi][ni][c] = 0.f;

    auto issue = [&](int buf, int k0) {
#pragma unroll
        for (int r = 0; r < 2; r++) {
            int idx = tid + (r << 8);      // 0..511
            int row = idx >> 2, c = idx & 3;
            uint32_t soff = (uint32_t)((buf * TILEB + row * SAB) * 2 + c * 16);
            const char* ga = (const char*)(A + (size_t)(m0 + row) * DD + k0) + c * 16;
            const char* gb = (const char*)(W + (size_t)(n0 + row) * DD + k0) + c * 16;
            CP_ASYNC16(as_base + soff, ga);
            CP_ASYNC16(bs_base + soff, gb);
        }
        CP_COMMIT();
    };

    issue(0, 0);
    for (int k0 = 0; k0 < DD; k0 += KCB) {
        int buf = (k0 / KCB) & 1;
        bool has_next = (k0 + KCB) < DD;
        if (has_next) {
            issue(buf ^ 1, k0 + KCB);
            CP_WAIT(1);
        } else {
            CP_WAIT(0);
        }
        __syncthreads();

        uint32_t abase = as_base + (uint32_t)(buf * TILEB * 2);
        uint32_t bbase = bs_base + (uint32_t)(buf * TILEB * 2);
#pragma unroll
        for (int ks = 0; ks < KCB; ks += 16) {
            uint32_t af[4][4], bf[4][2];
#pragma unroll
            for (int mi = 0; mi < 4; mi++)
                LDMX4(af[mi][0], af[mi][1], af[mi][2], af[mi][3],
                      abase + a_off[mi] + ks * 2);
#pragma unroll
            for (int nip = 0; nip < 2; nip++)
                LDMX4(bf[2 * nip][0], bf[2 * nip][1], bf[2 * nip + 1][0], bf[2 * nip + 1][1],
                      bbase + b_off[nip] + ks * 2);
#pragma unroll
            for (int mi = 0; mi < 4; mi++)
#pragma unroll
                for (int ni = 0; ni < 4; ni++)
                    mma_bf16(acc[mi][ni], af[mi], bf[ni]);
        }
        __syncthreads();
    }
}

// ---------------------------------------------------------------------------
// Kernel 1: QKV projection (bf16 mma) + RoPE + scatter
// ---------------------------------------------------------------------------
__global__ __launch_bounds__(256) void qkv_rope_mma_kernel(
    const float* __restrict__ sinb, const float* __restrict__ cosb)
{
    __shared__ __nv_bfloat16 As[2 * TILEB];
    __shared__ __nv_bfloat16 Bs[2 * TILEB];

    const int m0 = blockIdx.y << 7;
    const int n0 = blockIdx.x << 7;
    const int z  = blockIdx.z;
    const __nv_bfloat16* W = (z == 0) ? g_wqb : (z == 1 ? g_wkb : g_wvb);

    float acc[4][4][4];
    gemm_mainloop_bf16(acc, g_xb, W, m0, n0, As, Bs);

    const int tid = threadIdx.x, wid = tid >> 5, lane = tid & 31;
    const int wm = wid & 1, wn = wid >> 1;
    const int gid = lane >> 2, tig = lane & 3;
    const float qs = (z == 0) ? 0.125f : 1.0f;

#pragma unroll
    for (int mi = 0; mi < 4; mi++) {
#pragma unroll
        for (int half = 0; half < 2; half++) {
            int m  = m0 + wm * 64 + mi * 16 + gid + half * 8;
            int bb = m >> 11;
            int s  = m & (SS - 1);
#pragma unroll
            for (int ni = 0; ni < 4; ni++) {
                int n  = n0 + wn * 32 + ni * 8 + 2 * tig;   // even col
                int h  = n >> 6;
                int hd = n & 63;
                int ir = hd >> 1;
                float sn = sinb[s * (HDIM / 2) + ir];
                float cs = cosb[s * (HDIM / 2) + ir];
                float x1 = acc[mi][ni][half * 2 + 0];
                float x2 = acc[mi][ni][half * 2 + 1];
                float o1 = (x1 * cs - x2 * sn) * qs;
                float o2 = (x2 * cs + x1 * sn) * qs;
                if (z < 2) {
                    __nv_bfloat16* outp = (z == 0) ? g_qb : g_kb;
                    size_t base = ((size_t)(bb * HH + h) * SS + s) * HDIM + hd;
                    *reinterpret_cast<uint32_t*>(&outp[base]) = pack_bf16(o1, o2);
                } else {
                    size_t base = ((size_t)(bb * HH + h) * HDIM + hd) * SS + s;
                    g_vtb[base]      = __float2bfloat16_rn(o1);
                    g_vtb[base + SS] = __float2bfloat16_rn(o2);
                }
            }
        }
    }
}

// ---------------------------------------------------------------------------
// Kernel 3: O-proj (bf16 mma) + bias + residual -> g_x (fp32)
// ---------------------------------------------------------------------------
__global__ __launch_bounds__(256) void oproj_mma_kernel(
    const float* __restrict__ hidden, const float* __restrict__ bo)
{
    __shared__ __nv_bfloat16 As[2 * TILEB];
    __shared__ __nv_bfloat16 Bs[2 * TILEB];

    const int m0 = blockIdx.y << 7;
    const int n0 = blockIdx.x << 7;

    float acc[4][4][4];
    gemm_mainloop_bf16(acc, g_ctxb, g_wob, m0, n0, As, Bs);

    const int tid = threadIdx.x, wid = tid >> 5, lane = tid & 31;
    const int wm = wid & 1, wn = wid >> 1;
    const int gid = lane >> 2, tig = lane & 3;

#pragma unroll
    for (int mi = 0; mi < 4; mi++) {
#pragma unroll
        for (int half = 0; half < 2; half++) {
            int m = m0 + wm * 64 + mi * 16 + gid + half * 8;
#pragma unroll
            for (int ni = 0; ni < 4; ni++) {
                int n = n0 + wn * 32 + ni * 8 + 2 * tig;
                float2 hv = *reinterpret_cast<const float2*>(&hidden[(size_t)m * DD + n]);
                float2 bv = *reinterpret_cast<const float2*>(&bo[n]);
                float2 o;
                o.x = acc[mi][ni][half * 2 + 0] + bv.x + hv.x;
                o.y = acc[mi][ni][half * 2 + 1] + bv.y + hv.y;
                *reinterpret_cast<float2*>(&g_x[(size_t)m * DD + n]) = o;
            }
        }
    }
}

// ---------------------------------------------------------------------------
// Kernel 2: flash attention, bf16 fragments via ldmatrix, cp.async K/V
// double buffer. Block: one (b,h) x 128 q rows; 8 warps x 16 rows.
// dyn smem: Ks[2][64][72], VsT[2][64][72], Pw[128][72]  (bf16) = 55296 B
// ---------------------------------------------------------------------------
#define KSTRB 72
#define AT_TILE (64 * KSTRB)
#define ATTN_SMEM_B ((4 * AT_TILE + 128 * KSTRB) * 2)

__global__ __launch_bounds__(256) void attn_mma_kernel()
{
    extern __shared__ __nv_bfloat16 dyn[];
    __nv_bfloat16* Ks  = dyn;                    // [2][64][KSTRB]
    __nv_bfloat16* VsT = dyn + 2 * AT_TILE;      // [2][64][KSTRB]
    __nv_bfloat16* Pw  = dyn + 4 * AT_TILE;      // [128][KSTRB]

    const int tid = threadIdx.x, wid = tid >> 5, lane = tid & 31;
    const int gid = lane >> 2, tig = lane & 3;
    const int q0 = blockIdx.x << 7;
    const int bh = blockIdx.y;
    const __nv_bfloat16* qp = g_qb  + (size_t)bh * SS * HDIM;
    const __nv_bfloat16* kp = g_kb  + (size_t)bh * SS * HDIM;
    const __nv_bfloat16* vp = g_vtb + (size_t)bh * HDIM * SS;

    const uint32_t ks_base = smem_u32(Ks);
    const uint32_t vs_base = smem_u32(VsT);
    const uint32_t pw_base = smem_u32(Pw);

    // per-lane ldmatrix offsets
    // A-style (Q/P): row=(l&15), col=(l>>4)*8, within warp's 16-row band
    const uint32_t ap_off = (uint32_t)(((wid * 16 + (lane & 15)) * KSTRB + (lane >> 4) * 8) * 2);
    // B-style (K/V): per 16-row pair block
    const uint32_t kb_off = (uint32_t)((((lane & 7) + ((lane >> 4) & 1) * 8) * KSTRB
                                        + ((lane >> 3) & 1) * 8) * 2);

    // stage Q tile [128][64] bf16 into Pw
#pragma unroll
    for (int r = 0; r < 4; r++) {
        int idx = tid + (r << 8);             // 0..1023 chunks of 8 bf16
        int row = idx >> 3, c = idx & 7;
        *reinterpret_cast<uint4*>(&Pw[row * KSTRB + c * 8]) =
            *reinterpret_cast<const uint4*>(&qp[(size_t)(q0 + row) * HDIM + c * 8]);
    }
    __syncthreads();

    uint32_t qf[4][4];
#pragma unroll
    for (int kk = 0; kk < 4; kk++)
        LDMX4(qf[kk][0], qf[kk][1], qf[kk][2], qf[kk][3],
              pw_base + ap_off + kk * 32);   // kk*16 elems * 2B

    float oacc[8][4];
#pragma unroll
    for (int ni = 0; ni < 8; ni++)
#pragma unroll
        for (int c = 0; c < 4; c++) oacc[ni][c] = 0.f;
    float mrow[2] = {-1e30f, -1e30f};
    float lrow[2] = {0.f, 0.f};

    auto issue = [&](int buf, int kt) {
#pragma unroll
        for (int r = 0; r < 2; r++) {
            int c = tid + (r << 8);          // 0..511
            int row = c >> 3, col = (c & 7) * 8;
            uint32_t so = (uint32_t)(((buf * 64 + row) * KSTRB + col) * 2);
            CP_ASYNC16(ks_base + so, kp + (size_t)(kt + row) * HDIM + col);
            CP_ASYNC16(vs_base + so, vp + (size_t)row * SS + kt + col);
        }
        CP_COMMIT();
    };

    issue(0, 0);
    for (int t = 0; t < SS / 64; t++) {
        int buf = t & 1;
        if (t + 1 < SS / 64) {
            issue(buf ^ 1, (t + 1) * 64);
            CP_WAIT(1);
        } else {
            CP_WAIT(0);
        }
        __syncthreads();

        uint32_t kb = ks_base + (uint32_t)(buf * AT_TILE * 2);
        uint32_t vb = vs_base + (uint32_t)(buf * AT_TILE * 2);

        // S = Q K^T  (per warp: 16 x 64), q pre-scaled by 1/8
        float sacc[8][4];
#pragma unroll
        for (int ni = 0; ni < 8; ni++)
#pragma unroll
            for (int c = 0; c < 4; c++) sacc[ni][c] = 0.f;

#pragma unroll
        for (int kk = 0; kk < 4; kk++) {
            uint32_t kf[8][2];
#pragma unroll
            for (int nip = 0; nip < 4; nip++)
                LDMX4(kf[2 * nip][0], kf[2 * nip][1], kf[2 * nip + 1][0], kf[2 * nip + 1][1],
                      kb + kb_off + (uint32_t)(nip * 16 * KSTRB * 2) + kk * 32);
#pragma unroll
            for (int ni = 0; ni < 8; ni++)
                mma_bf16(sacc[ni], qf[kk], kf[ni]);
        }

        // online softmax (rows gid and gid+8 of this warp's 16)
        float mx0 = -1e30f, mx1 = -1e30f;
#pragma unroll
        for (int ni = 0; ni < 8; ni++) {
            mx0 = fmaxf(mx0, fmaxf(sacc[ni][0], sacc[ni][1]));
            mx1 = fmaxf(mx1, fmaxf(sacc[ni][2], sacc[ni][3]));
        }
#pragma unroll
        for (int off = 1; off <= 2; off <<= 1) {
            mx0 = fmaxf(mx0, __shfl_xor_sync(0xffffffffu, mx0, off));
            mx1 = fmaxf(mx1, __shfl_xor_sync(0xffffffffu, mx1, off));
        }
        float mn0 = fmaxf(mrow[0], mx0), mn1 = fmaxf(mrow[1], mx1);
        float corr0 = __expf(mrow[0] - mn0), corr1 = __expf(mrow[1] - mn1);
        float rs0 = 0.f, rs1 = 0.f;
        __nv_bfloat16* Pq = Pw + wid * 16 * KSTRB;
#pragma unroll
        for (int ni = 0; ni < 8; ni++) {
            float p0 = __expf(sacc[ni][0] - mn0);
            float p1 = __expf(sacc[ni][1] - mn0);
            float p2 = __expf(sacc[ni][2] - mn1);
            float p3 = __expf(sacc[ni][3] - mn1);
            rs0 += p0 + p1; rs1 += p2 + p3;
            int c = ni * 8 + 2 * tig;
            *reinterpret_cast<uint32_t*>(Pq + gid * KSTRB + c)       = pack_bf16(p0, p1);
            *reinterpret_cast<uint32_t*>(Pq + (gid + 8) * KSTRB + c) = pack_bf16(p2, p3);
        }
#pragma unroll
        for (int off = 1; off <= 2; off <<= 1) {
            rs0 += __shfl_xor_sync(0xffffffffu, rs0, off);
            rs1 += __shfl_xor_sync(0xffffffffu, rs1, off);
        }
        lrow[0] = lrow[0] * corr0 + rs0;
        lrow[1] = lrow[1] * corr1 + rs1;
        mrow[0] = mn0; mrow[1] = mn1;
#pragma unroll
        for (int ni = 0; ni < 8; ni++) {
            oacc[ni][0] *= corr0; oacc[ni][1] *= corr0;
            oacc[ni][2] *= corr1; oacc[ni][3] *= corr1;
        }
        __syncwarp();

        // O += P V   (per warp: 16 q x 64 dims, k = 64 keys)
#pragma unroll
        for (int kk = 0; kk < 4; kk++) {
            uint32_t pf[4];
            LDMX4(pf[0], pf[1], pf[2], pf[3], pw_base + ap_off + kk * 32);
            uint32_t vf[8][2];
#pragma unroll
            for (int nip = 0; nip < 4; nip++)
                LDMX4(vf[2 * nip][0], vf[2 * nip][1], vf[2 * nip + 1][0], vf[2 * nip + 1][1],
                      vb + kb_off + (uint32_t)(nip * 16 * KSTRB * 2) + kk * 32);
#pragma unroll
            for (int ni = 0; ni < 8; ni++)
                mma_bf16(oacc[ni], pf, vf[ni]);
        }
        __syncthreads();
    }

    // write ctx [B,S,D] as bf16
    const int bb = bh >> 4;
    const int h  = bh & 15;
    float inv0 = 1.0f / lrow[0];
    float inv1 = 1.0f / lrow[1];
    int s0 = q0 + wid * 16 + gid;
#pragma unroll
    for (int ni = 0; ni < 8; ni++) {
        int d = ni * 8 + 2 * tig;
        size_t base0 = ((size_t)bb * SS + s0) * DD + h * HDIM + d;
        size_t base1 = ((size_t)bb * SS + s0 + 8) * DD + h * HDIM + d;
        *reinterpret_cast<uint32_t*>(&g_ctxb[base0]) =
            pack_bf16(oacc[ni][0] * inv0, oacc[ni][1] * inv0);
        *reinterpret_cast<uint32_t*>(&g_ctxb[base1]) =
            pack_bf16(oacc[ni][2] * inv1, oacc[ni][3] * inv1);
    }
}

// ---------------------------------------------------------------------------
// Kernel 4: RMS norm per row of g_x
// ---------------------------------------------------------------------------
__global__ __launch_bounds__(256) void rmsnorm_kernel(
    const float* __restrict__ scale, float* __restrict__ out)
{
    __shared__ float red[8];
    __shared__ float s_tot;
    const int row = blockIdx.x;
    const int tid = threadIdx.x;
    const float4* xr = reinterpret_cast<const float4*>(g_x + (size_t)row * DD);
    float4 xv = xr[tid];
    float ss = xv.x*xv.x + xv.y*xv.y + xv.z*xv.z + xv.w*xv.w;
#pragma unroll
    for (int off = 16; off > 0; off >>= 1)
        ss += __shfl_xor_sync(0xffffffffu, ss, off);
    if ((tid & 31) == 0) red[tid >> 5] = ss;
    __syncthreads();
    if (tid == 0) {
        float t = 0.f;
#pragma unroll
        for (int w = 0; w < 8; w++) t += red[w];
        s_tot = t;
    }
    __syncthreads();
    float rms = sqrtf(s_tot * (1.0f / DD));
    float inv = 1.0f / (rms + RMS_EPS);
    float4 sc = reinterpret_cast<const float4*>(scale)[tid];
    float4 ov;
    ov.x = xv.x * sc.x * inv;
    ov.y = xv.y * sc.y * inv;
    ov.z = xv.z * sc.z * inv;
    ov.w = xv.w * sc.w * inv;
    reinterpret_cast<float4*>(out)[(size_t)row * (DD / 4) + tid] = ov;
}

// ---------------------------------------------------------------------------
extern "C" void kernel_launch(void* const* d_in, const int* in_sizes, int n_in,
                              void* d_out, int out_size)
{
    const float* hidden = (const float*)d_in[0];
    const float* sinb   = (const float*)d_in[1];
    const float* cosb   = (const float*)d_in[2];
    const float* wq     = (const float*)d_in[3];
    const float* wk     = (const float*)d_in[4];
    const float* wv     = (const float*)d_in[5];
    const float* wo     = (const float*)d_in[6];
    const float* bo     = (const float*)d_in[7];
    const float* scale  = (const float*)d_in[8];
    float* out = (float*)d_out;

    cudaFuncSetAttribute(attn_mma_kernel,
                         cudaFuncAttributeMaxDynamicSharedMemorySize, ATTN_SMEM_B);

    const int n4h = MM * DD / 4;
    const int n4w = DD * DD / 4;
    cvt_h_kernel<<<(n4h + 255) / 256, 256>>>((const float4*)hidden);
    cvt_w_kernel<<<dim3((n4w + 255) / 256, 4), 256>>>(
        (const float4*)wq, (const float4*)wk, (const float4*)wv, (const float4*)wo);

    qkv_rope_mma_kernel<<<dim3(DD / 128, MM / 128, 3), 256>>>(sinb, cosb);
    attn_mma_kernel<<<dim3(SS / 128, BB * HH), 256, ATTN_SMEM_B>>>();
    oproj_mma_kernel<<<dim3(DD / 128, MM / 128), 256>>>(hidden, bo);
    rmsnorm_kernel<<<MM, 256>>>(scale, out);
}

// round 7
// speedup vs baseline: 6.8402x; 1.0270x over previous
#include <cuda_runtime.h>
#include <cuda_bf16.h>
#include <math.h>
#include <stdint.h>

// Problem constants
#define BB   2
#define SS   2048
#define DD   1024
#define HH   16
#define HDIM 64
#define MM   (BB*SS)          // 4096 rows
#define RMS_EPS 1e-8f

// Scratch
__device__ __nv_bfloat16 g_xb[MM*DD];          // hidden in bf16
__device__ __nv_bfloat16 g_wqb[DD*DD];
__device__ __nv_bfloat16 g_wkb[DD*DD];
__device__ __nv_bfloat16 g_wvb[DD*DD];
__device__ __nv_bfloat16 g_wob[DD*DD];
__device__ __nv_bfloat16 g_qb[BB*HH*SS*HDIM];  // [B,H,S,HD], pre-scaled by 1/8
__device__ __nv_bfloat16 g_kb[BB*HH*SS*HDIM];  // [B,H,S,HD]
__device__ __nv_bfloat16 g_vtb[BB*HH*HDIM*SS]; // [B,H,HD,S]  (transposed V)
__device__ __nv_bfloat16 g_ctxb[MM*DD];        // [B,S,D]
__device__ float g_x[MM*DD];                   // post-proj + residual (fp32)

// ---------------------------------------------------------------------------
// helpers
// ---------------------------------------------------------------------------
__device__ __forceinline__ uint32_t smem_u32(const void* p) {
    uint32_t a;
    asm("{ .reg .u64 t; cvta.to.shared.u64 t, %1; cvt.u32.u64 %0, t; }"
        : "=r"(a) : "l"(p));
    return a;
}

// D += A(16x16) * B(16x8), bf16 inputs, fp32 accum
__device__ __forceinline__ void mma_bf16(float* d, const uint32_t* a, const uint32_t* b) {
    asm volatile(
        "mma.sync.aligned.m16n8k16.row.col.f32.bf16.bf16.f32 "
        "{%0,%1,%2,%3}, {%4,%5,%6,%7}, {%8,%9}, {%0,%1,%2,%3};"
        : "+f"(d[0]), "+f"(d[1]), "+f"(d[2]), "+f"(d[3])
        : "r"(a[0]), "r"(a[1]), "r"(a[2]), "r"(a[3]), "r"(b[0]), "r"(b[1]));
}

#define LDMX4(r0, r1, r2, r3, addr) \
    asm volatile("ldmatrix.sync.aligned.m8n8.x4.shared.b16 {%0,%1,%2,%3}, [%4];" \
                 : "=r"(r0), "=r"(r1), "=r"(r2), "=r"(r3) : "r"(addr))

#define CP_ASYNC16(saddr, gptr) \
    asm volatile("cp.async.cg.shared.global [%0], [%1], 16;" :: "r"(saddr), "l"(gptr))
#define CP_COMMIT() asm volatile("cp.async.commit_group;")
#define CP_WAIT(N)  asm volatile("cp.async.wait_group %0;" :: "n"(N))

__device__ __forceinline__ uint32_t pack_bf16(float x, float y) {
    __nv_bfloat162 p = __floats2bfloat162_rn(x, y);
    return *reinterpret_cast<uint32_t*>(&p);
}

// ---------------------------------------------------------------------------
// Kernel 0: fp32 -> bf16 conversion prepass (hidden; weights fused 2D)
// ---------------------------------------------------------------------------
__global__ __launch_bounds__(256) void cvt_h_kernel(const float4* __restrict__ src)
{
    int i = blockIdx.x * 256 + threadIdx.x;
    if (i < MM * DD / 4) {
        float4 v = src[i];
        uint2 o;
        o.x = pack_bf16(v.x, v.y);
        o.y = pack_bf16(v.z, v.w);
        reinterpret_cast<uint2*>(g_xb)[i] = o;
    }
}

__global__ __launch_bounds__(256) void cvt_w_kernel(
    const float4* __restrict__ wq, const float4* __restrict__ wk,
    const float4* __restrict__ wv, const float4* __restrict__ wo)
{
    int i = blockIdx.x * 256 + threadIdx.x;
    if (i >= DD * DD / 4) return;
    int z = blockIdx.y;
    const float4* s = (z == 0) ? wq : (z == 1) ? wk : (z == 2) ? wv : wo;
    __nv_bfloat16* dp = (z == 0) ? g_wqb : (z == 1) ? g_wkb : (z == 2) ? g_wvb : g_wob;
    float4 v = s[i];
    uint2 o;
    o.x = pack_bf16(v.x, v.y);
    o.y = pack_bf16(v.z, v.w);
    reinterpret_cast<uint2*>(dp)[i] = o;
}

// ---------------------------------------------------------------------------
// bf16 GEMM mainloop: 128x128 tile of A[M,1024] @ W[1024,1024]^T
// 256 threads = 8 warps (2x4), warp tile 64x32, KC=32 bf16, double buffer,
// ldmatrix fragment loads.
// ---------------------------------------------------------------------------
#define KCB   32
#define SAB   40                       // smem row stride (bf16) = 80B
#define TILEB (128 * SAB)              // bf16 per buffer

__device__ __forceinline__ void gemm_mainloop_bf16(
    float (&acc)[4][4][4],
    const __nv_bfloat16* __restrict__ A, const __nv_bfloat16* __restrict__ W,
    int m0, int n0, __nv_bfloat16* As, __nv_bfloat16* Bs)
{
    const int tid  = threadIdx.x;
    const int wid  = tid >> 5, lane = tid & 31;
    const int wm = wid & 1, wn = wid >> 1;

    const uint32_t as_base = smem_u32(As);
    const uint32_t bs_base = smem_u32(Bs);

    uint32_t a_off[4], b_off[2];
#pragma unroll
    for (int mi = 0; mi < 4; mi++)
        a_off[mi] = (uint32_t)(((wm * 64 + mi * 16 + (lane & 15)) * SAB + (lane >> 4) * 8) * 2);
#pragma unroll
    for (int nip = 0; nip < 2; nip++)
        b_off[nip] = (uint32_t)(((wn * 32 + nip * 16 + (lane & 7) + ((lane >> 4) & 1) * 8) * SAB
                                 + ((lane >> 3) & 1) * 8) * 2);

#pragma unroll
    for (int mi = 0; mi < 4; mi++)
#pragma unroll
        for (int ni = 0; ni < 4; ni++)
#pragma unroll
            for (int c = 0; c < 4; c++) acc[mi][ni][c] = 0.f;

    auto issue = [&](int buf, int k0) {
#pragma unroll
        for (int r = 0; r < 2; r++) {
            int idx = tid + (r << 8);      // 0..511
            int row = idx >> 2, c = idx & 3;
            uint32_t soff = (uint32_t)((buf * TILEB + row * SAB) * 2 + c * 16);
            const char* ga = (const char*)(A + (size_t)(m0 + row) * DD + k0) + c * 16;
            const char* gb = (const char*)(W + (size_t)(n0 + row) * DD + k0) + c * 16;
            CP_ASYNC16(as_base + soff, ga);
            CP_ASYNC16(bs_base + soff, gb);
        }
        CP_COMMIT();
    };

    issue(0, 0);
    for (int k0 = 0; k0 < DD; k0 += KCB) {
        int buf = (k0 / KCB) & 1;
        bool has_next = (k0 + KCB) < DD;
        if (has_next) {
            issue(buf ^ 1, k0 + KCB);
            CP_WAIT(1);
        } else {
            CP_WAIT(0);
        }
        __syncthreads();

        uint32_t abase = as_base + (uint32_t)(buf * TILEB * 2);
        uint32_t bbase = bs_base + (uint32_t)(buf * TILEB * 2);
#pragma unroll
        for (int ks = 0; ks < KCB; ks += 16) {
            uint32_t af[4][4], bf[4][2];
#pragma unroll
            for (int mi = 0; mi < 4; mi++)
                LDMX4(af[mi][0], af[mi][1], af[mi][2], af[mi][3],
                      abase + a_off[mi] + ks * 2);
#pragma unroll
            for (int nip = 0; nip < 2; nip++)
                LDMX4(bf[2 * nip][0], bf[2 * nip][1], bf[2 * nip + 1][0], bf[2 * nip + 1][1],
                      bbase + b_off[nip] + ks * 2);
#pragma unroll
            for (int mi = 0; mi < 4; mi++)
#pragma unroll
                for (int ni = 0; ni < 4; ni++)
                    mma_bf16(acc[mi][ni], af[mi], bf[ni]);
        }
        __syncthreads();
    }
}

// ---------------------------------------------------------------------------
// Kernel 1: QKV projection (bf16 mma) + RoPE + scatter
// ---------------------------------------------------------------------------
__global__ __launch_bounds__(256) void qkv_rope_mma_kernel(
    const float* __restrict__ sinb, const float* __restrict__ cosb)
{
    __shared__ __nv_bfloat16 As[2 * TILEB];
    __shared__ __nv_bfloat16 Bs[2 * TILEB];

    const int m0 = blockIdx.y << 7;
    const int n0 = blockIdx.x << 7;
    const int z  = blockIdx.z;
    const __nv_bfloat16* W = (z == 0) ? g_wqb : (z == 1 ? g_wkb : g_wvb);

    float acc[4][4][4];
    gemm_mainloop_bf16(acc, g_xb, W, m0, n0, As, Bs);

    const int tid = threadIdx.x, wid = tid >> 5, lane = tid & 31;
    const int wm = wid & 1, wn = wid >> 1;
    const int gid = lane >> 2, tig = lane & 3;
    const float qs = (z == 0) ? 0.125f : 1.0f;

#pragma unroll
    for (int mi = 0; mi < 4; mi++) {
#pragma unroll
        for (int half = 0; half < 2; half++) {
            int m  = m0 + wm * 64 + mi * 16 + gid + half * 8;
            int bb = m >> 11;
            int s  = m & (SS - 1);
#pragma unroll
            for (int ni = 0; ni < 4; ni++) {
                int n  = n0 + wn * 32 + ni * 8 + 2 * tig;   // even col
                int h  = n >> 6;
                int hd = n & 63;
                int ir = hd >> 1;
                float sn = sinb[s * (HDIM / 2) + ir];
                float cs = cosb[s * (HDIM / 2) + ir];
                float x1 = acc[mi][ni][half * 2 + 0];
                float x2 = acc[mi][ni][half * 2 + 1];
                float o1 = (x1 * cs - x2 * sn) * qs;
                float o2 = (x2 * cs + x1 * sn) * qs;
                if (z < 2) {
                    __nv_bfloat16* outp = (z == 0) ? g_qb : g_kb;
                    size_t base = ((size_t)(bb * HH + h) * SS + s) * HDIM + hd;
                    *reinterpret_cast<uint32_t*>(&outp[base]) = pack_bf16(o1, o2);
                } else {
                    size_t base = ((size_t)(bb * HH + h) * HDIM + hd) * SS + s;
                    g_vtb[base]      = __float2bfloat16_rn(o1);
                    g_vtb[base + SS] = __float2bfloat16_rn(o2);
                }
            }
        }
    }
}

// ---------------------------------------------------------------------------
// Kernel 3: O-proj (bf16 mma) + bias + residual -> g_x (fp32)
// ---------------------------------------------------------------------------
__global__ __launch_bounds__(256) void oproj_mma_kernel(
    const float* __restrict__ hidden, const float* __restrict__ bo)
{
    __shared__ __nv_bfloat16 As[2 * TILEB];
    __shared__ __nv_bfloat16 Bs[2 * TILEB];

    const int m0 = blockIdx.y << 7;
    const int n0 = blockIdx.x << 7;

    float acc[4][4][4];
    gemm_mainloop_bf16(acc, g_ctxb, g_wob, m0, n0, As, Bs);

    const int tid = threadIdx.x, wid = tid >> 5, lane = tid & 31;
    const int wm = wid & 1, wn = wid >> 1;
    const int gid = lane >> 2, tig = lane & 3;

#pragma unroll
    for (int mi = 0; mi < 4; mi++) {
#pragma unroll
        for (int half = 0; half < 2; half++) {
            int m = m0 + wm * 64 + mi * 16 + gid + half * 8;
#pragma unroll
            for (int ni = 0; ni < 4; ni++) {
                int n = n0 + wn * 32 + ni * 8 + 2 * tig;
                float2 hv = *reinterpret_cast<const float2*>(&hidden[(size_t)m * DD + n]);
                float2 bv = *reinterpret_cast<const float2*>(&bo[n]);
                float2 o;
                o.x = acc[mi][ni][half * 2 + 0] + bv.x + hv.x;
                o.y = acc[mi][ni][half * 2 + 1] + bv.y + hv.y;
                *reinterpret_cast<float2*>(&g_x[(size_t)m * DD + n]) = o;
            }
        }
    }
}

// ---------------------------------------------------------------------------
// Kernel 2: flash attention — P kept entirely in registers (C-frag == A-frag),
// bf16 ldmatrix fragments, cp.async K/V double buffer.
// Block: one (b,h) x 128 q rows; 8 warps x 16 rows. Key tiles of 64.
// smem: Ks[2][64][72] + VsT[2][64][72] bf16 = 36864 B (static).
// ---------------------------------------------------------------------------
#define KSTRB 72
#define AT_TILE (64 * KSTRB)

__global__ __launch_bounds__(256) void attn_mma_kernel()
{
    __shared__ __nv_bfloat16 Ks [2 * AT_TILE];
    __shared__ __nv_bfloat16 VsT[2 * AT_TILE];

    const int tid = threadIdx.x, wid = tid >> 5, lane = tid & 31;
    const int gid = lane >> 2, tig = lane & 3;
    const int q0 = blockIdx.x << 7;
    const int bh = blockIdx.y;
    const __nv_bfloat16* qp = g_qb  + (size_t)bh * SS * HDIM;
    const __nv_bfloat16* kp = g_kb  + (size_t)bh * SS * HDIM;
    const __nv_bfloat16* vp = g_vtb + (size_t)bh * HDIM * SS;

    const uint32_t ks_base = smem_u32(Ks);
    const uint32_t vs_base = smem_u32(VsT);

    // ldmatrix lane offsets
    const uint32_t ap_off = (uint32_t)(((wid * 16 + (lane & 15)) * KSTRB + (lane >> 4) * 8) * 2);
    const uint32_t kb_off = (uint32_t)((((lane & 7) + ((lane >> 4) & 1) * 8) * KSTRB
                                        + ((lane >> 3) & 1) * 8) * 2);

    // stage Q tile [128][64] through Ks (both buffers = 128 rows), grab frags
#pragma unroll
    for (int r = 0; r < 4; r++) {
        int idx = tid + (r << 8);             // 0..1023 chunks of 8 bf16
        int row = idx >> 3, c = idx & 7;
        *reinterpret_cast<uint4*>(&Ks[row * KSTRB + c * 8]) =
            *reinterpret_cast<const uint4*>(&qp[(size_t)(q0 + row) * HDIM + c * 8]);
    }
    __syncthreads();

    uint32_t qf[4][4];
#pragma unroll
    for (int kk = 0; kk < 4; kk++)
        LDMX4(qf[kk][0], qf[kk][1], qf[kk][2], qf[kk][3], ks_base + ap_off + kk * 32);
    __syncthreads();   // Q frags in regs; Ks may be overwritten now

    float oacc[8][4];
#pragma unroll
    for (int ni = 0; ni < 8; ni++)
#pragma unroll
        for (int c = 0; c < 4; c++) oacc[ni][c] = 0.f;
    float mrow[2] = {-1e30f, -1e30f};
    float lrow[2] = {0.f, 0.f};

    auto issue = [&](int buf, int kt) {
#pragma unroll
        for (int r = 0; r < 2; r++) {
            int c = tid + (r << 8);          // 0..511
            int row = c >> 3, col = (c & 7) * 8;
            uint32_t so = (uint32_t)(((buf * 64 + row) * KSTRB + col) * 2);
            CP_ASYNC16(ks_base + so, kp + (size_t)(kt + row) * HDIM + col);
            CP_ASYNC16(vs_base + so, vp + (size_t)row * SS + kt + col);
        }
        CP_COMMIT();
    };

    issue(0, 0);
    for (int t = 0; t < SS / 64; t++) {
        int buf = t & 1;
        if (t + 1 < SS / 64) {
            issue(buf ^ 1, (t + 1) * 64);
            CP_WAIT(1);
        } else {
            CP_WAIT(0);
        }
        __syncthreads();

        uint32_t kb = ks_base + (uint32_t)(buf * AT_TILE * 2);
        uint32_t vb = vs_base + (uint32_t)(buf * AT_TILE * 2);

        // S = Q K^T  (per warp: 16 x 64), q pre-scaled by 1/8
        float sacc[8][4];
#pragma unroll
        for (int ni = 0; ni < 8; ni++)
#pragma unroll
            for (int c = 0; c < 4; c++) sacc[ni][c] = 0.f;

#pragma unroll
        for (int kk = 0; kk < 4; kk++) {
            uint32_t kf[8][2];
#pragma unroll
            for (int nip = 0; nip < 4; nip++)
                LDMX4(kf[2 * nip][0], kf[2 * nip][1], kf[2 * nip + 1][0], kf[2 * nip + 1][1],
                      kb + kb_off + (uint32_t)(nip * 16 * KSTRB * 2) + kk * 32);
#pragma unroll
            for (int ni = 0; ni < 8; ni++)
                mma_bf16(sacc[ni], qf[kk], kf[ni]);
        }

        // online softmax; exp'd probabilities stay in sacc (registers)
        float mx0 = -1e30f, mx1 = -1e30f;
#pragma unroll
        for (int ni = 0; ni < 8; ni++) {
            mx0 = fmaxf(mx0, fmaxf(sacc[ni][0], sacc[ni][1]));
            mx1 = fmaxf(mx1, fmaxf(sacc[ni][2], sacc[ni][3]));
        }
#pragma unroll
        for (int off = 1; off <= 2; off <<= 1) {
            mx0 = fmaxf(mx0, __shfl_xor_sync(0xffffffffu, mx0, off));
            mx1 = fmaxf(mx1, __shfl_xor_sync(0xffffffffu, mx1, off));
        }
        float mn0 = fmaxf(mrow[0], mx0), mn1 = fmaxf(mrow[1], mx1);
        float corr0 = __expf(mrow[0] - mn0), corr1 = __expf(mrow[1] - mn1);
        float rs0 = 0.f, rs1 = 0.f;
#pragma unroll
        for (int ni = 0; ni < 8; ni++) {
            sacc[ni][0] = __expf(sacc[ni][0] - mn0);
            sacc[ni][1] = __expf(sacc[ni][1] - mn0);
            sacc[ni][2] = __expf(sacc[ni][2] - mn1);
            sacc[ni][3] = __expf(sacc[ni][3] - mn1);
            rs0 += sacc[ni][0] + sacc[ni][1];
            rs1 += sacc[ni][2] + sacc[ni][3];
        }
#pragma unroll
        for (int off = 1; off <= 2; off <<= 1) {
            rs0 += __shfl_xor_sync(0xffffffffu, rs0, off);
            rs1 += __shfl_xor_sync(0xffffffffu, rs1, off);
        }
        lrow[0] = lrow[0] * corr0 + rs0;
        lrow[1] = lrow[1] * corr1 + rs1;
        mrow[0] = mn0; mrow[1] = mn1;
#pragma unroll
        for (int ni = 0; ni < 8; ni++) {
            oacc[ni][0] *= corr0; oacc[ni][1] *= corr0;
            oacc[ni][2] *= corr1; oacc[ni][3] *= corr1;
        }

        // O += P V : P A-fragments built directly from sacc registers
#pragma unroll
        for (int kk = 0; kk < 4; kk++) {
            uint32_t pf[4];
            pf[0] = pack_bf16(sacc[2 * kk][0],     sacc[2 * kk][1]);
            pf[1] = pack_bf16(sacc[2 * kk][2],     sacc[2 * kk][3]);
            pf[2] = pack_bf16(sacc[2 * kk + 1][0], sacc[2 * kk + 1][1]);
            pf[3] = pack_bf16(sacc[2 * kk + 1][2], sacc[2 * kk + 1][3]);
            uint32_t vf[8][2];
#pragma unroll
            for (int nip = 0; nip < 4; nip++)
                LDMX4(vf[2 * nip][0], vf[2 * nip][1], vf[2 * nip + 1][0], vf[2 * nip + 1][1],
                      vb + kb_off + (uint32_t)(nip * 16 * KSTRB * 2) + kk * 32);
#pragma unroll
            for (int ni = 0; ni < 8; ni++)
                mma_bf16(oacc[ni], pf, vf[ni]);
        }
        __syncthreads();
    }

    // write ctx [B,S,D] as bf16
    const int bb = bh >> 4;
    const int h  = bh & 15;
    float inv0 = 1.0f / lrow[0];
    float inv1 = 1.0f / lrow[1];
    int s0 = q0 + wid * 16 + gid;
#pragma unroll
    for (int ni = 0; ni < 8; ni++) {
        int d = ni * 8 + 2 * tig;
        size_t base0 = ((size_t)bb * SS + s0) * DD + h * HDIM + d;
        size_t base1 = ((size_t)bb * SS + s0 + 8) * DD + h * HDIM + d;
        *reinterpret_cast<uint32_t*>(&g_ctxb[base0]) =
            pack_bf16(oacc[ni][0] * inv0, oacc[ni][1] * inv0);
        *reinterpret_cast<uint32_t*>(&g_ctxb[base1]) =
            pack_bf16(oacc[ni][2] * inv1, oacc[ni][3] * inv1);
    }
}

// ---------------------------------------------------------------------------
// Kernel 4: RMS norm per row of g_x
// ---------------------------------------------------------------------------
__global__ __launch_bounds__(256) void rmsnorm_kernel(
    const float* __restrict__ scale, float* __restrict__ out)
{
    __shared__ float red[8];
    __shared__ float s_tot;
    const int row = blockIdx.x;
    const int tid = threadIdx.x;
    const float4* xr = reinterpret_cast<const float4*>(g_x + (size_t)row * DD);
    float4 xv = xr[tid];
    float ss = xv.x*xv.x + xv.y*xv.y + xv.z*xv.z + xv.w*xv.w;
#pragma unroll
    for (int off = 16; off > 0; off >>= 1)
        ss += __shfl_xor_sync(0xffffffffu, ss, off);
    if ((tid & 31) == 0) red[tid >> 5] = ss;
    __syncthreads();
    if (tid == 0) {
        float t = 0.f;
#pragma unroll
        for (int w = 0; w < 8; w++) t += red[w];
        s_tot = t;
    }
    __syncthreads();
    float rms = sqrtf(s_tot * (1.0f / DD));
    float inv = 1.0f / (rms + RMS_EPS);
    float4 sc = reinterpret_cast<const float4*>(scale)[tid];
    float4 ov;
    ov.x = xv.x * sc.x * inv;
    ov.y = xv.y * sc.y * inv;
    ov.z = xv.z * sc.z * inv;
    ov.w = xv.w * sc.w * inv;
    reinterpret_cast<float4*>(out)[(size_t)row * (DD / 4) + tid] = ov;
}

// ---------------------------------------------------------------------------
extern "C" void kernel_launch(void* const* d_in, const int* in_sizes, int n_in,
                              void* d_out, int out_size)
{
    const float* hidden = (const float*)d_in[0];
    const float* sinb   = (const float*)d_in[1];
    const float* cosb   = (const float*)d_in[2];
    const float* wq     = (const float*)d_in[3];
    const float* wk     = (const float*)d_in[4];
    const float* wv     = (const float*)d_in[5];
    const float* wo     = (const float*)d_in[6];
    const float* bo     = (const float*)d_in[7];
    const float* scale  = (const float*)d_in[8];
    float* out = (float*)d_out;

    const int n4h = MM * DD / 4;
    const int n4w = DD * DD / 4;
    cvt_h_kernel<<<(n4h + 255) / 256, 256>>>((const float4*)hidden);
    cvt_w_kernel<<<dim3((n4w + 255) / 256, 4), 256>>>(
        (const float4*)wq, (const float4*)wk, (const float4*)wv, (const float4*)wo);

    qkv_rope_mma_kernel<<<dim3(DD / 128, MM / 128, 3), 256>>>(sinb, cosb);
    attn_mma_kernel<<<dim3(SS / 128, BB * HH), 256>>>();
    oproj_mma_kernel<<<dim3(DD / 128, MM / 128), 256>>>(hidden, bo);
    rmsnorm_kernel<<<MM, 256>>>(scale, out);
}